// round 5
// baseline (speedup 1.0000x reference)
#include <cuda_runtime.h>
#include <cuda_bf16.h>
#include <math.h>
#include <stdint.h>

#define NS      65536
#define NBUS    32
#define HD      256
#define MT      64            // samples per CTA
#define NCTA    (NS / MT)
#define THREADS 256
#define NCH     8             // n-chunks of 32 over HD=256

// ---- smem map (dynamic, 229376 B total) ----
// A tiles: 3 streams (h,p,q) x hi/lo, each [64 m][256 k] bf16 = 32768 B
#define A_T(s,hl) (((s)*2+(hl))*32768)
#define B1_T(hl)  (196608 + (hl)*16384)   // W1^T chunk [32 n][256 k] bf16 hi/lo
#define RED_OFF   196608                  // per-chunk z-partial exchange [3][64][34] f32 (aliases B1)
#define RW        34
#define SMEM_TOTAL 229376
// final-phase aliases (A region is dead by then)
#define O_OFF   0             // out      [64][32] f32
#define OT_OFF  8192          // out_t    [64][32] f32
#define OTT_OFF 16384         // out_tt   [64][32] f32
#define SCS_OFF 24576         // sin      [64][33] f32
#define SCC_OFF 33024         // cos      [64][33] f32

static __device__ __forceinline__ uint32_t s2u(const void* p) {
    uint32_t a;
    asm("{ .reg .u64 t; cvta.to.shared.u64 t, %1; cvt.u32.u64 %0, t; }" : "=r"(a) : "l"(p));
    return a;
}
static __device__ __forceinline__ uint32_t pk(float a, float b) {
    __nv_bfloat162 t = __floats2bfloat162_rn(a, b);
    return *reinterpret_cast<uint32_t*>(&t);
}
static __device__ __forceinline__ float bhi(float v) {
    return __bfloat162float(__float2bfloat16(v));
}
static __device__ __forceinline__ float tanh_fast(float x) {
    // 1 - 2/(e^{2x}+1): MUFU EX2 + RCP, rel err ~1e-6; saturates correctly.
    return 1.0f - 2.0f / (__expf(2.0f * x) + 1.0f);
}
static __device__ __forceinline__ void ldsm4(uint32_t* r, uint32_t a) {
    asm volatile("ldmatrix.sync.aligned.m8n8.x4.shared.b16 {%0,%1,%2,%3}, [%4];"
                 : "=r"(r[0]), "=r"(r[1]), "=r"(r[2]), "=r"(r[3]) : "r"(a));
}
static __device__ __forceinline__ void mma16816(float* d, const uint32_t* a,
                                                uint32_t b0, uint32_t b1) {
    asm volatile(
        "mma.sync.aligned.m16n8k16.row.col.f32.bf16.bf16.f32 "
        "{%0,%1,%2,%3}, {%4,%5,%6,%7}, {%8,%9}, {%0,%1,%2,%3};"
        : "+f"(d[0]), "+f"(d[1]), "+f"(d[2]), "+f"(d[3])
        : "r"(a[0]), "r"(a[1]), "r"(a[2]), "r"(a[3]), "r"(b0), "r"(b1));
}

__global__ void __launch_bounds__(THREADS, 1) pinn_hmma_kernel(
    const float* __restrict__ t_in, const float* __restrict__ power,
    const float* __restrict__ W0, const float* __restrict__ b0,
    const float* __restrict__ W1, const float* __restrict__ b1,
    const float* __restrict__ W2, const float* __restrict__ b2,
    const float* __restrict__ lam_m, const float* __restrict__ lam_d,
    const float* __restrict__ lam_b, const float* __restrict__ bwi,
    float* __restrict__ out_d, float* __restrict__ out_dt, float* __restrict__ out_ph)
{
    extern __shared__ __align__(1024) char smc[];
    const uint32_t sb = s2u(smc);

    const int tid   = threadIdx.x;
    const int lane  = tid & 31;
    const int wid   = tid >> 5;
    const int warpM = wid & 3;     // m-tile: rows warpM*16 .. +15
    const int wk    = wid >> 2;    // K-half for layer-1; n-half owner for epilogue
    const int base  = blockIdx.x * MT;

    // ============ Phase A: generate h/p/q split tiles (once per CTA) ============
    // element (m,k): byte off = m*512 + (((k>>3)^(m&7))<<4) + (k&7)*2
    {
        const int gm  = tid >> 2;            // 0..63
        const int gk0 = (tid & 3) * 64;      // k range start
        const float t = __ldg(&t_in[base + gm]);
        const float x = fmaf(t, 0.1f, -1.0f);
        #pragma unroll 4
        for (int kk = 0; kk < 64; kk += 2) {
            const int k = gk0 + kk;
            float hv[2], pv[2], qv[2];
            #pragma unroll
            for (int e = 0; e < 2; e++) {
                const float w = __ldg(&W0[k + e]);
                const float d = 0.1f * w;
                const float z = fmaf(x, w, __ldg(&b0[k + e]));
                const float h = tanh_fast(z);
                const float u = 1.0f - h * h;
                hv[e] = h; pv[e] = u * d; qv[e] = -2.0f * h * u * d * d;
            }
            const uint32_t off = (uint32_t)(gm * 512 + ((((k >> 3) ^ (gm & 7))) << 4) + (k & 7) * 2);
            float h0 = bhi(hv[0]), h1 = bhi(hv[1]);
            *(uint32_t*)(smc + A_T(0,0) + off) = pk(h0, h1);
            *(uint32_t*)(smc + A_T(0,1) + off) = pk(hv[0] - h0, hv[1] - h1);
            h0 = bhi(pv[0]); h1 = bhi(pv[1]);
            *(uint32_t*)(smc + A_T(1,0) + off) = pk(h0, h1);
            *(uint32_t*)(smc + A_T(1,1) + off) = pk(pv[0] - h0, pv[1] - h1);
            h0 = bhi(qv[0]); h1 = bhi(qv[1]);
            *(uint32_t*)(smc + A_T(2,0) + off) = pk(h0, h1);
            *(uint32_t*)(smc + A_T(2,1) + off) = pk(qv[0] - h0, qv[1] - h1);
        }
    }

    // ldmatrix address components (x4: lanes 0-15 rows, 16-31 select k-half)
    const int l16  = lane & 15;
    const int csel = lane >> 4;
    const uint32_t xr   = (uint32_t)(l16 & 7);
    const uint32_t rowA = (uint32_t)((warpM * 16 + l16) * 512);
    const uint32_t rowB = (uint32_t)(l16 * 512);           // chunk n rows 0..15; +8192 for 16..31
    const int q  = lane & 3;       // C/A-frag col-pair & B-frag k-pair
    const int br = lane >> 2;      // C/A-frag row & B-frag n

    // layer-2 accumulators (partial over this wk's k2 columns)
    float acc2[3][4][4];
    #pragma unroll
    for (int s = 0; s < 3; s++)
        #pragma unroll
        for (int nb = 0; nb < 4; nb++)
            #pragma unroll
            for (int e = 0; e < 4; e++) acc2[s][nb][e] = 0.0f;

    float* R = (float*)(smc + RED_OFF);

    // ============ main loop over 8 n-chunks of 32 columns ============
    for (int c = 0; c < NCH; c++) {
        __syncthreads();   // prev chunk: B1/R reads done; phase-A writes done (c=0)

        // ---- load W1^T chunk: [32 n][256 k] bf16 hi/lo ----
        {
            const int n = tid & 31;
            #pragma unroll 4
            for (int i = 0; i < 16; i++) {
                const int kp = (tid >> 5) + i * 8;
                const int k  = kp * 2;
                const float v0 = __ldg(&W1[(size_t)k * HD + c * 32 + n]);
                const float v1 = __ldg(&W1[(size_t)(k + 1) * HD + c * 32 + n]);
                const float h0 = bhi(v0), h1 = bhi(v1);
                const uint32_t off = (uint32_t)(n * 512 + ((((k >> 3) ^ (n & 7))) << 4) + (k & 7) * 2);
                *(uint32_t*)(smc + B1_T(0) + off) = pk(h0, h1);
                *(uint32_t*)(smc + B1_T(1) + off) = pk(v0 - h0, v1 - h1);
            }
        }
        __syncthreads();

        // ---- layer-1: partial z/zp/zq [16m x 32n] over this warp's K-half ----
        float acc[3][4][4];
        #pragma unroll
        for (int s = 0; s < 3; s++)
            #pragma unroll
            for (int t = 0; t < 4; t++)
                #pragma unroll
                for (int e = 0; e < 4; e++) acc[s][t][e] = 0.0f;

        #pragma unroll 2
        for (int ktl = 0; ktl < 8; ktl++) {
            const int kt = wk * 8 + ktl;
            const uint32_t co = (uint32_t)(((kt * 2 + csel) ^ xr) << 4);
            uint32_t ah[3][4], al[3][4], bh[8], bl[8];
            #pragma unroll
            for (int s = 0; s < 3; s++) {
                ldsm4(ah[s], sb + A_T(s,0) + rowA + co);
                ldsm4(al[s], sb + A_T(s,1) + rowA + co);
            }
            ldsm4(bh,     sb + B1_T(0) + rowB + co);
            ldsm4(bh + 4, sb + B1_T(0) + rowB + 8192 + co);
            ldsm4(bl,     sb + B1_T(1) + rowB + co);
            ldsm4(bl + 4, sb + B1_T(1) + rowB + 8192 + co);
            #pragma unroll
            for (int s = 0; s < 3; s++) {
                #pragma unroll
                for (int t = 0; t < 4; t++) {
                    const int g = (t >> 1) * 4;          // 0 for n0-15 frags, 4 for n16-31
                    const int u = t & 1;
                    mma16816(acc[s][t], ah[s], bh[g + u], bh[g + u + 2]);
                    mma16816(acc[s][t], al[s], bh[g + u], bh[g + u + 2]);
                    mma16816(acc[s][t], ah[s], bl[g + u], bl[g + u + 2]);
                }
            }
        }
        __syncthreads();   // all B1 reads done -> R may alias it

        // ---- cross-K exchange: write the n-half we do NOT own ----
        {
            const int t_o = (1 - wk) * 2;
            #pragma unroll
            for (int s = 0; s < 3; s++)
                #pragma unroll
                for (int tt = 0; tt < 2; tt++)
                    #pragma unroll
                    for (int rp = 0; rp < 2; rp++) {
                        const int row = warpM * 16 + br + rp * 8;
                        const int col = (t_o + tt) * 8 + 2 * q;
                        *(float2*)&R[(s * 64 + row) * RW + col] =
                            make_float2(acc[s][t_o + tt][rp * 2], acc[s][t_o + tt][rp * 2 + 1]);
                    }
        }
        __syncthreads();

        // ---- complete owned half, tanh chain in registers ----
        const int jg = c * 32 + wk * 16;     // this warp's 16 j-columns
        float vg[2][4], vp[2][4], vq[2][4];
        #pragma unroll
        for (int tt = 0; tt < 2; tt++) {
            const int t_w = wk * 2 + tt;
            const float b1a = __ldg(&b1[jg + tt * 8 + 2 * q]);
            const float b1b = __ldg(&b1[jg + tt * 8 + 2 * q + 1]);
            #pragma unroll
            for (int rp = 0; rp < 2; rp++) {
                const int row = warpM * 16 + br + rp * 8;
                const int col = t_w * 8 + 2 * q;
                const float2 rz = *(const float2*)&R[(0 * 64 + row) * RW + col];
                const float2 rzp = *(const float2*)&R[(1 * 64 + row) * RW + col];
                const float2 rzq = *(const float2*)&R[(2 * 64 + row) * RW + col];
                #pragma unroll
                for (int e2 = 0; e2 < 2; e2++) {
                    const int e = rp * 2 + e2;
                    const float zh = acc[0][t_w][e] + (e2 ? rz.y : rz.x) + (e2 ? b1b : b1a);
                    const float zp = acc[1][t_w][e] + (e2 ? rzp.y : rzp.x);
                    const float zq = acc[2][t_w][e] + (e2 ? rzq.y : rzq.x);
                    const float g  = tanh_fast(zh);
                    const float u  = 1.0f - g * g;
                    vg[tt][e] = g;
                    vp[tt][e] = u * zp;
                    vq[tt][e] = u * fmaf(-2.0f * g * zp, zp, zq);
                }
            }
        }

        // ---- layer-2: C2 += G(k2=16) @ W2 ; A-frags direct from C-frags ----
        uint32_t w2h[4][2], w2l[4][2];
        #pragma unroll
        for (int nb = 0; nb < 4; nb++) {
            const int bus = nb * 8 + br;
            const float v0 = __ldg(&W2[(size_t)(jg + 2 * q)     * NBUS + bus]);
            const float v1 = __ldg(&W2[(size_t)(jg + 2 * q + 1) * NBUS + bus]);
            const float v2 = __ldg(&W2[(size_t)(jg + 2 * q + 8) * NBUS + bus]);
            const float v3 = __ldg(&W2[(size_t)(jg + 2 * q + 9) * NBUS + bus]);
            const float h0 = bhi(v0), h1 = bhi(v1), h2 = bhi(v2), h3 = bhi(v3);
            w2h[nb][0] = pk(h0, h1);           w2h[nb][1] = pk(h2, h3);
            w2l[nb][0] = pk(v0 - h0, v1 - h1); w2l[nb][1] = pk(v2 - h2, v3 - h3);
        }
        #pragma unroll
        for (int s = 0; s < 3; s++) {
            const float (*v)[4] = (s == 0) ? vg : (s == 1) ? vp : vq;
            uint32_t a2h[4], a2l[4];
            float x0 = bhi(v[0][0]), x1 = bhi(v[0][1]);
            a2h[0] = pk(x0, x1); a2l[0] = pk(v[0][0] - x0, v[0][1] - x1);
            x0 = bhi(v[0][2]); x1 = bhi(v[0][3]);
            a2h[1] = pk(x0, x1); a2l[1] = pk(v[0][2] - x0, v[0][3] - x1);
            x0 = bhi(v[1][0]); x1 = bhi(v[1][1]);
            a2h[2] = pk(x0, x1); a2l[2] = pk(v[1][0] - x0, v[1][1] - x1);
            x0 = bhi(v[1][2]); x1 = bhi(v[1][3]);
            a2h[3] = pk(x0, x1); a2l[3] = pk(v[1][2] - x0, v[1][3] - x1);
            #pragma unroll
            for (int nb = 0; nb < 4; nb++) {
                mma16816(acc2[s][nb], a2h, w2h[nb][0], w2h[nb][1]);
                mma16816(acc2[s][nb], a2l, w2h[nb][0], w2h[nb][1]);
                mma16816(acc2[s][nb], a2h, w2l[nb][0], w2l[nb][1]);
            }
        }
    }

    // ============ cross-warpK k2 reduction + physics ============
    __syncthreads();   // all A/B1/R smem reads done -> safe to alias
    float* f_o   = (float*)(smc + O_OFF);
    float* f_ot  = (float*)(smc + OT_OFF);
    float* f_ott = (float*)(smc + OTT_OFF);
    float* scs   = (float*)(smc + SCS_OFF);
    float* scc   = (float*)(smc + SCC_OFF);

    if (wk == 0) {
        #pragma unroll
        for (int s = 0; s < 3; s++) {
            float* dst = (s == 0) ? f_o : (s == 1) ? f_ot : f_ott;
            #pragma unroll
            for (int nb = 0; nb < 4; nb++)
                #pragma unroll
                for (int e = 0; e < 4; e++) {
                    const int row = warpM * 16 + br + ((e >> 1) << 3);
                    const int bus = nb * 8 + 2 * q + (e & 1);
                    dst[row * NBUS + bus] = acc2[s][nb][e];
                }
        }
    }
    __syncthreads();
    if (wk == 1) {
        #pragma unroll
        for (int s = 0; s < 3; s++) {
            float* dst = (s == 0) ? f_o : (s == 1) ? f_ot : f_ott;
            #pragma unroll
            for (int nb = 0; nb < 4; nb++)
                #pragma unroll
                for (int e = 0; e < 4; e++) {
                    const int row = warpM * 16 + br + ((e >> 1) << 3);
                    const int bus = nb * 8 + 2 * q + (e & 1);
                    float v = dst[row * NBUS + bus] + acc2[s][nb][e];
                    if (s == 0) v += __ldg(&b2[bus]);
                    dst[row * NBUS + bus] = v;
                }
        }
    }
    __syncthreads();

    // sin/cos tables
    #pragma unroll
    for (int i = 0; i < 8; i++) {
        const int cell = tid * 8 + i;
        const int m = cell >> 5, bus = cell & 31;
        float sv, cv;
        __sincosf(f_o[cell], &sv, &cv);
        scs[m * 33 + bus] = sv;
        scc[m * 33 + bus] = cv;
    }
    __syncthreads();

    // physics: thread -> sample pm, buses pb..pb+7
    const int pm = tid >> 2;
    const int pb = (tid & 3) * 8;
    #pragma unroll
    for (int g4 = 0; g4 < 2; g4++) {
        float4 vo, vt, vp4;
        float* po = &vo.x; float* pt = &vt.x; float* pp = &vp4.x;
        const float4 pw = __ldg((const float4*)(power + (size_t)(base + pm) * NBUS + pb + g4 * 4));
        const float* ppw = &pw.x;
        #pragma unroll
        for (int e = 0; e < 4; e++) {
            const int bus = pb + g4 * 4 + e;
            const float o   = f_o  [pm * NBUS + bus];
            const float ot  = f_ot [pm * NBUS + bus];
            const float ott = f_ott[pm * NBUS + bus];
            float accC = 0.0f, accS = 0.0f;
            #pragma unroll
            for (int j = 0; j < NBUS; j++) {
                const float bl2 = __ldg(&lam_b[bus * NBUS + j]);
                accC = fmaf(bl2, scc[pm * 33 + j], accC);
                accS = fmaf(bl2, scs[pm * 33 + j], accS);
            }
            const float conn = scs[pm * 33 + bus] * accC - scc[pm * 33 + bus] * accS;
            const float lm = __ldg(&lam_m[bus]) * __ldg(&bwi[bus]);
            const float ld = __ldg(&lam_d[bus]);
            po[e] = o;
            pt[e] = ot;
            pp[e] = fmaf(lm, ott, fmaf(ld, ot, conn - ppw[e]));
        }
        const size_t gi = (size_t)(base + pm) * NBUS + pb + g4 * 4;
        *(float4*)(out_d  + gi) = vo;
        *(float4*)(out_dt + gi) = vt;
        *(float4*)(out_ph + gi) = vp4;
    }
}

extern "C" void kernel_launch(void* const* d_in, const int* in_sizes, int n_in,
                              void* d_out, int out_size) {
    const float* t_in  = (const float*)d_in[0];
    const float* power = (const float*)d_in[1];
    const float* W0    = (const float*)d_in[2];
    const float* b0    = (const float*)d_in[3];
    const float* W1    = (const float*)d_in[4];
    const float* b1    = (const float*)d_in[5];
    const float* W2    = (const float*)d_in[6];
    const float* b2    = (const float*)d_in[7];
    const float* lam_m = (const float*)d_in[8];
    const float* lam_d = (const float*)d_in[9];
    const float* lam_b = (const float*)d_in[10];
    const float* bwi   = (const float*)d_in[11];

    float* out  = (float*)d_out;
    float* outt = out  + (size_t)NS * NBUS;
    float* outp = outt + (size_t)NS * NBUS;

    cudaFuncSetAttribute(pinn_hmma_kernel, cudaFuncAttributeMaxDynamicSharedMemorySize, SMEM_TOTAL);
    pinn_hmma_kernel<<<NCTA, THREADS, SMEM_TOTAL>>>(t_in, power, W0, b0, W1, b1, W2, b2,
                                                    lam_m, lam_d, lam_b, bwi,
                                                    out, outt, outp);
}

// round 6
// speedup vs baseline: 1.5416x; 1.5416x over previous
#include <cuda_runtime.h>
#include <cuda_bf16.h>
#include <math.h>
#include <stdint.h>

#define NS      65536
#define NBUS    32
#define HD      256
#define MT      64            // samples per CTA
#define NCTA    (NS / MT)
#define THREADS 256
#define NCH     8             // n-chunks of 32 over HD=256

// ---- smem map (dynamic, 229376 B total) ----
// A tiles: 3 streams (h,p,q) x hi/lo, each [64 m][256 k] bf16 = 32768 B
#define A_T(s,hl) (((s)*2+(hl))*32768)
#define B1_T(hl)  (196608 + (hl)*16384)   // W1^T chunk [32 n][256 k] bf16 hi/lo
#define SMEM_TOTAL 229376
// final-phase aliases (A region is dead by then)
#define O_OFF   0             // out      [64][32] f32
#define OT_OFF  8192          // out_t    [64][32] f32
#define OTT_OFF 16384         // out_tt   [64][32] f32
#define SCS_OFF 24576         // sin      [64][33] f32
#define SCC_OFF 33024         // cos      [64][33] f32

static __device__ __forceinline__ uint32_t s2u(const void* p) {
    uint32_t a;
    asm("{ .reg .u64 t; cvta.to.shared.u64 t, %1; cvt.u32.u64 %0, t; }" : "=r"(a) : "l"(p));
    return a;
}
static __device__ __forceinline__ uint32_t pk(float a, float b) {
    __nv_bfloat162 t = __floats2bfloat162_rn(a, b);
    return *reinterpret_cast<uint32_t*>(&t);
}
static __device__ __forceinline__ float bhi(float v) {
    return __bfloat162float(__float2bfloat16(v));
}
static __device__ __forceinline__ float tanh_fast(float x) {
    // 1 - 2/(e^{2x}+1): MUFU EX2 + RCP, rel err ~1e-6; saturates correctly.
    return 1.0f - 2.0f / (__expf(2.0f * x) + 1.0f);
}
static __device__ __forceinline__ void ldsm4(uint32_t* r, uint32_t a) {
    asm volatile("ldmatrix.sync.aligned.m8n8.x4.shared.b16 {%0,%1,%2,%3}, [%4];"
                 : "=r"(r[0]), "=r"(r[1]), "=r"(r[2]), "=r"(r[3]) : "r"(a));
}
static __device__ __forceinline__ void mma16816(float* d, const uint32_t* a,
                                                uint32_t b0, uint32_t b1) {
    asm volatile(
        "mma.sync.aligned.m16n8k16.row.col.f32.bf16.bf16.f32 "
        "{%0,%1,%2,%3}, {%4,%5,%6,%7}, {%8,%9}, {%0,%1,%2,%3};"
        : "+f"(d[0]), "+f"(d[1]), "+f"(d[2]), "+f"(d[3])
        : "r"(a[0]), "r"(a[1]), "r"(a[2]), "r"(a[3]), "r"(b0), "r"(b1));
}

__global__ void __launch_bounds__(THREADS, 1) pinn_hmma_kernel(
    const float* __restrict__ t_in, const float* __restrict__ power,
    const float* __restrict__ W0, const float* __restrict__ b0,
    const float* __restrict__ W1, const float* __restrict__ b1,
    const float* __restrict__ W2, const float* __restrict__ b2,
    const float* __restrict__ lam_m, const float* __restrict__ lam_d,
    const float* __restrict__ lam_b, const float* __restrict__ bwi,
    float* __restrict__ out_d, float* __restrict__ out_dt, float* __restrict__ out_ph)
{
    extern __shared__ __align__(1024) char smc[];
    const uint32_t sb = s2u(smc);

    const int tid   = threadIdx.x;
    const int lane  = tid & 31;
    const int wid   = tid >> 5;
    const int warpM = wid & 3;     // m-tile: rows warpM*16 .. +15
    const int warpN = wid >> 2;    // n-tile within 32-chunk: cols warpN*16 .. +15
    const int base  = blockIdx.x * MT;

    // ============ Phase A: generate h/p/q split tiles (once per CTA) ============
    // element (m,k): byte off = m*512 + (((k>>3)^(m&7))<<4) + (k&7)*2
    {
        const int gm  = tid >> 2;            // 0..63
        const int gk0 = (tid & 3) * 64;      // k range start
        const float t = __ldg(&t_in[base + gm]);
        const float x = fmaf(t, 0.1f, -1.0f);
        #pragma unroll 4
        for (int kk = 0; kk < 64; kk += 2) {
            const int k = gk0 + kk;
            float hv[2], pv[2], qv[2];
            #pragma unroll
            for (int e = 0; e < 2; e++) {
                const float w = __ldg(&W0[k + e]);
                const float d = 0.1f * w;
                const float z = fmaf(x, w, __ldg(&b0[k + e]));
                const float h = tanh_fast(z);
                const float u = 1.0f - h * h;
                hv[e] = h; pv[e] = u * d; qv[e] = -2.0f * h * u * d * d;
            }
            const uint32_t off = (uint32_t)(gm * 512 + ((((k >> 3) ^ (gm & 7))) << 4) + (k & 7) * 2);
            float h0 = bhi(hv[0]), h1 = bhi(hv[1]);
            *(uint32_t*)(smc + A_T(0,0) + off) = pk(h0, h1);
            *(uint32_t*)(smc + A_T(0,1) + off) = pk(hv[0] - h0, hv[1] - h1);
            h0 = bhi(pv[0]); h1 = bhi(pv[1]);
            *(uint32_t*)(smc + A_T(1,0) + off) = pk(h0, h1);
            *(uint32_t*)(smc + A_T(1,1) + off) = pk(pv[0] - h0, pv[1] - h1);
            h0 = bhi(qv[0]); h1 = bhi(qv[1]);
            *(uint32_t*)(smc + A_T(2,0) + off) = pk(h0, h1);
            *(uint32_t*)(smc + A_T(2,1) + off) = pk(qv[0] - h0, qv[1] - h1);
        }
    }

    // per-thread ldmatrix address components (canonical x4: lanes 0-15 rows, 16-31 k-half)
    const int l16 = lane & 15;
    const int csel = lane >> 4;
    const uint32_t xr   = (uint32_t)(l16 & 7);
    const uint32_t rowA = (uint32_t)((warpM * 16 + l16) * 512);
    const uint32_t rowB = (uint32_t)((warpN * 16 + l16) * 512);
    const int q  = lane & 3;       // C/A-frag col-pair & B-frag k-pair
    const int br = lane >> 2;      // C/A-frag row & B-frag n

    // layer-2 accumulators: out/out_t/out_tt [16m x 32bus] per warp (partial over k2)
    float acc2[3][4][4];
    #pragma unroll
    for (int s = 0; s < 3; s++)
        #pragma unroll
        for (int nb = 0; nb < 4; nb++)
            #pragma unroll
            for (int e = 0; e < 4; e++) acc2[s][nb][e] = 0.0f;

    // ============ main loop over 8 n-chunks of 32 columns ============
    for (int c = 0; c < NCH; c++) {
        __syncthreads();   // prior chunk's B1 reads (and phase-A writes) complete

        // ---- load W1^T chunk: [32 n][256 k] bf16 hi/lo ----
        {
            const int n = tid & 31;
            #pragma unroll 4
            for (int i = 0; i < 16; i++) {
                const int kp = (tid >> 5) + i * 8;
                const int k  = kp * 2;
                const float v0 = __ldg(&W1[(size_t)k * HD + c * 32 + n]);
                const float v1 = __ldg(&W1[(size_t)(k + 1) * HD + c * 32 + n]);
                const float h0 = bhi(v0), h1 = bhi(v1);
                const uint32_t off = (uint32_t)(n * 512 + ((((k >> 3) ^ (n & 7))) << 4) + (k & 7) * 2);
                *(uint32_t*)(smc + B1_T(0) + off) = pk(h0, h1);
                *(uint32_t*)(smc + B1_T(1) + off) = pk(v0 - h0, v1 - h1);
            }
        }
        __syncthreads();

        // ---- layer-1: z/zp/zq [16m x 16n] per warp, K = 256 ----
        float acc[3][2][4];
        #pragma unroll
        for (int s = 0; s < 3; s++)
            #pragma unroll
            for (int t = 0; t < 2; t++)
                #pragma unroll
                for (int e = 0; e < 4; e++) acc[s][t][e] = 0.0f;

        #pragma unroll 4
        for (int kt = 0; kt < 16; kt++) {
            const uint32_t co = (uint32_t)((((kt * 2 + csel)) ^ xr) << 4);
            uint32_t ah[3][4], al[3][4], bh[4], bl[4];
            #pragma unroll
            for (int s = 0; s < 3; s++) {
                ldsm4(ah[s], sb + A_T(s,0) + rowA + co);
                ldsm4(al[s], sb + A_T(s,1) + rowA + co);
            }
            ldsm4(bh, sb + B1_T(0) + rowB + co);
            ldsm4(bl, sb + B1_T(1) + rowB + co);
            #pragma unroll
            for (int s = 0; s < 3; s++) {
                #pragma unroll
                for (int t = 0; t < 2; t++) {
                    mma16816(acc[s][t], ah[s], bh[t], bh[t + 2]);
                    mma16816(acc[s][t], al[s], bh[t], bh[t + 2]);
                    mma16816(acc[s][t], ah[s], bl[t], bl[t + 2]);
                }
            }
        }

        // ---- in-register epilogue: bias + tanh chain -> G fragments ----
        const int jg = c * 32 + warpN * 16;   // this warp's 16 j-columns (k2 tile)
        float vg[2][4], vp[2][4], vq[2][4];
        #pragma unroll
        for (int t = 0; t < 2; t++) {
            const float b1a = __ldg(&b1[jg + t * 8 + 2 * q]);
            const float b1b = __ldg(&b1[jg + t * 8 + 2 * q + 1]);
            #pragma unroll
            for (int e = 0; e < 4; e++) {
                const float zh = acc[0][t][e] + ((e & 1) ? b1b : b1a);
                const float zp = acc[1][t][e];
                const float zq = acc[2][t][e];
                const float g  = tanh_fast(zh);
                const float u  = 1.0f - g * g;
                vg[t][e] = g;
                vp[t][e] = u * zp;
                vq[t][e] = u * fmaf(-2.0f * g * zp, zp, zq);
            }
        }

        // ---- layer-2: C2 += G(k2=16) @ W2 ; A-frags direct from C-frags ----
        uint32_t w2h[4][2], w2l[4][2];
        #pragma unroll
        for (int nb = 0; nb < 4; nb++) {
            const int bus = nb * 8 + br;
            const float v0 = __ldg(&W2[(size_t)(jg + 2 * q)     * NBUS + bus]);
            const float v1 = __ldg(&W2[(size_t)(jg + 2 * q + 1) * NBUS + bus]);
            const float v2 = __ldg(&W2[(size_t)(jg + 2 * q + 8) * NBUS + bus]);
            const float v3 = __ldg(&W2[(size_t)(jg + 2 * q + 9) * NBUS + bus]);
            const float h0 = bhi(v0), h1 = bhi(v1), h2 = bhi(v2), h3 = bhi(v3);
            w2h[nb][0] = pk(h0, h1);          w2h[nb][1] = pk(h2, h3);
            w2l[nb][0] = pk(v0 - h0, v1 - h1); w2l[nb][1] = pk(v2 - h2, v3 - h3);
        }
        #pragma unroll
        for (int s = 0; s < 3; s++) {
            const float (*v)[4] = (s == 0) ? vg : (s == 1) ? vp : vq;
            uint32_t a2h[4], a2l[4];
            // a0={(r,k01) t0 c01}, a1={t0 c23}, a2={t1 c01}, a3={t1 c23}
            float x0 = bhi(v[0][0]), x1 = bhi(v[0][1]);
            a2h[0] = pk(x0, x1); a2l[0] = pk(v[0][0] - x0, v[0][1] - x1);
            x0 = bhi(v[0][2]); x1 = bhi(v[0][3]);
            a2h[1] = pk(x0, x1); a2l[1] = pk(v[0][2] - x0, v[0][3] - x1);
            x0 = bhi(v[1][0]); x1 = bhi(v[1][1]);
            a2h[2] = pk(x0, x1); a2l[2] = pk(v[1][0] - x0, v[1][1] - x1);
            x0 = bhi(v[1][2]); x1 = bhi(v[1][3]);
            a2h[3] = pk(x0, x1); a2l[3] = pk(v[1][2] - x0, v[1][3] - x1);
            #pragma unroll
            for (int nb = 0; nb < 4; nb++) {
                mma16816(acc2[s][nb], a2h, w2h[nb][0], w2h[nb][1]);
                mma16816(acc2[s][nb], a2l, w2h[nb][0], w2h[nb][1]);
                mma16816(acc2[s][nb], a2h, w2l[nb][0], w2l[nb][1]);
            }
        }
    }

    // ============ cross-warp k2 reduction + physics ============
    __syncthreads();   // all A/B1 smem reads done -> safe to alias
    float* f_o   = (float*)(smc + O_OFF);
    float* f_ot  = (float*)(smc + OT_OFF);
    float* f_ott = (float*)(smc + OTT_OFF);
    float* scs   = (float*)(smc + SCS_OFF);
    float* scc   = (float*)(smc + SCC_OFF);

    if (warpN == 0) {
        #pragma unroll
        for (int s = 0; s < 3; s++) {
            float* dst = (s == 0) ? f_o : (s == 1) ? f_ot : f_ott;
            #pragma unroll
            for (int nb = 0; nb < 4; nb++)
                #pragma unroll
                for (int e = 0; e < 4; e++) {
                    const int row = warpM * 16 + br + ((e >> 1) << 3);
                    const int bus = nb * 8 + 2 * q + (e & 1);
                    dst[row * NBUS + bus] = acc2[s][nb][e];
                }
        }
    }
    __syncthreads();
    if (warpN == 1) {
        #pragma unroll
        for (int s = 0; s < 3; s++) {
            float* dst = (s == 0) ? f_o : (s == 1) ? f_ot : f_ott;
            #pragma unroll
            for (int nb = 0; nb < 4; nb++)
                #pragma unroll
                for (int e = 0; e < 4; e++) {
                    const int row = warpM * 16 + br + ((e >> 1) << 3);
                    const int bus = nb * 8 + 2 * q + (e & 1);
                    float v = dst[row * NBUS + bus] + acc2[s][nb][e];
                    if (s == 0) v += __ldg(&b2[bus]);
                    dst[row * NBUS + bus] = v;
                }
        }
    }
    __syncthreads();

    // sin/cos tables
    #pragma unroll
    for (int i = 0; i < 8; i++) {
        const int cell = tid * 8 + i;
        const int m = cell >> 5, bus = cell & 31;
        float sv, cv;
        __sincosf(f_o[cell], &sv, &cv);
        scs[m * 33 + bus] = sv;
        scc[m * 33 + bus] = cv;
    }
    __syncthreads();

    // physics: thread -> sample pm, buses pb..pb+7
    const int pm = tid >> 2;
    const int pb = (tid & 3) * 8;
    #pragma unroll
    for (int g4 = 0; g4 < 2; g4++) {
        float4 vo, vt, vp4;
        float* po = &vo.x; float* pt = &vt.x; float* pp = &vp4.x;
        const float4 pw = __ldg((const float4*)(power + (size_t)(base + pm) * NBUS + pb + g4 * 4));
        const float* ppw = &pw.x;
        #pragma unroll
        for (int e = 0; e < 4; e++) {
            const int bus = pb + g4 * 4 + e;
            const float o   = f_o  [pm * NBUS + bus];
            const float ot  = f_ot [pm * NBUS + bus];
            const float ott = f_ott[pm * NBUS + bus];
            float accC = 0.0f, accS = 0.0f;
            #pragma unroll
            for (int j = 0; j < NBUS; j++) {
                const float bl2 = __ldg(&lam_b[bus * NBUS + j]);
                accC = fmaf(bl2, scc[pm * 33 + j], accC);
                accS = fmaf(bl2, scs[pm * 33 + j], accS);
            }
            const float conn = scs[pm * 33 + bus] * accC - scc[pm * 33 + bus] * accS;
            const float lm = __ldg(&lam_m[bus]) * __ldg(&bwi[bus]);
            const float ld = __ldg(&lam_d[bus]);
            po[e] = o;
            pt[e] = ot;
            pp[e] = fmaf(lm, ott, fmaf(ld, ot, conn - ppw[e]));
        }
        const size_t gi = (size_t)(base + pm) * NBUS + pb + g4 * 4;
        *(float4*)(out_d  + gi) = vo;
        *(float4*)(out_dt + gi) = vt;
        *(float4*)(out_ph + gi) = vp4;
    }
}

extern "C" void kernel_launch(void* const* d_in, const int* in_sizes, int n_in,
                              void* d_out, int out_size) {
    const float* t_in  = (const float*)d_in[0];
    const float* power = (const float*)d_in[1];
    const float* W0    = (const float*)d_in[2];
    const float* b0    = (const float*)d_in[3];
    const float* W1    = (const float*)d_in[4];
    const float* b1    = (const float*)d_in[5];
    const float* W2    = (const float*)d_in[6];
    const float* b2    = (const float*)d_in[7];
    const float* lam_m = (const float*)d_in[8];
    const float* lam_d = (const float*)d_in[9];
    const float* lam_b = (const float*)d_in[10];
    const float* bwi   = (const float*)d_in[11];

    float* out  = (float*)d_out;
    float* outt = out  + (size_t)NS * NBUS;
    float* outp = outt + (size_t)NS * NBUS;

    cudaFuncSetAttribute(pinn_hmma_kernel, cudaFuncAttributeMaxDynamicSharedMemorySize, SMEM_TOTAL);
    pinn_hmma_kernel<<<NCTA, THREADS, SMEM_TOTAL>>>(t_in, power, W0, b0, W1, b1, W2, b2,
                                                    lam_m, lam_d, lam_b, bwi,
                                                    out, outt, outp);
}

// round 7
// speedup vs baseline: 1.8671x; 1.2111x over previous
#include <cuda_runtime.h>
#include <cuda_bf16.h>
#include <math.h>
#include <stdint.h>

#define NS      65536
#define NBUS    32
#define HD      256
#define MT      64            // samples per CTA
#define NCTA    (NS / MT)
#define THREADS 256
#define NCH     8             // n-chunks of 32 over HD=256

// ---- smem map (dynamic, 229376 B total) ----
// A tiles: 3 streams (h,p,q) x hi/lo, each [64 m][256 k] bf16 = 32768 B
#define A_T(s,hl) (((s)*2+(hl))*32768)
#define B1_T(hl)  (196608 + (hl)*16384)   // W1^T chunk [32 n][256 k] bf16 hi/lo
#define SMEM_TOTAL 229376
// final-phase aliases (A region is dead by then)
#define O_OFF   0             // out      [64][32] f32
#define OT_OFF  8192          // out_t    [64][32] f32
#define OTT_OFF 16384         // out_tt   [64][32] f32
#define SCS_OFF 24576         // sin      [64][33] f32
#define SCC_OFF 33024         // cos      [64][33] f32

static __device__ __forceinline__ uint32_t s2u(const void* p) {
    uint32_t a;
    asm("{ .reg .u64 t; cvta.to.shared.u64 t, %1; cvt.u32.u64 %0, t; }" : "=r"(a) : "l"(p));
    return a;
}
static __device__ __forceinline__ uint32_t pk(float a, float b) {
    __nv_bfloat162 t = __floats2bfloat162_rn(a, b);
    return *reinterpret_cast<uint32_t*>(&t);
}
static __device__ __forceinline__ float bhi(float v) {
    return __bfloat162float(__float2bfloat16(v));
}
static __device__ __forceinline__ float tanh_fast(float x) {
    // 1 - 2/(e^{2x}+1) with MUFU EX2 + MUFU RCP (__fdividef), ~5 instr.
    // Saturates correctly: expf->inf => fdividef->0 => 1 ; expf->0 => -1.
    return 1.0f - __fdividef(2.0f, __expf(2.0f * x) + 1.0f);
}
static __device__ __forceinline__ void ldsm4(uint32_t* r, uint32_t a) {
    asm volatile("ldmatrix.sync.aligned.m8n8.x4.shared.b16 {%0,%1,%2,%3}, [%4];"
                 : "=r"(r[0]), "=r"(r[1]), "=r"(r[2]), "=r"(r[3]) : "r"(a));
}
static __device__ __forceinline__ void mma16816(float* d, const uint32_t* a,
                                                uint32_t b0, uint32_t b1) {
    asm volatile(
        "mma.sync.aligned.m16n8k16.row.col.f32.bf16.bf16.f32 "
        "{%0,%1,%2,%3}, {%4,%5,%6,%7}, {%8,%9}, {%0,%1,%2,%3};"
        : "+f"(d[0]), "+f"(d[1]), "+f"(d[2]), "+f"(d[3])
        : "r"(a[0]), "r"(a[1]), "r"(a[2]), "r"(a[3]), "r"(b0), "r"(b1));
}

__global__ void __launch_bounds__(THREADS, 1) pinn_hmma_kernel(
    const float* __restrict__ t_in, const float* __restrict__ power,
    const float* __restrict__ W0, const float* __restrict__ b0,
    const float* __restrict__ W1, const float* __restrict__ b1,
    const float* __restrict__ W2, const float* __restrict__ b2,
    const float* __restrict__ lam_m, const float* __restrict__ lam_d,
    const float* __restrict__ lam_b, const float* __restrict__ bwi,
    float* __restrict__ out_d, float* __restrict__ out_dt, float* __restrict__ out_ph)
{
    extern __shared__ __align__(1024) char smc[];
    const uint32_t sb = s2u(smc);

    const int tid   = threadIdx.x;
    const int lane  = tid & 31;
    const int wid   = tid >> 5;
    const int warpM = wid & 3;     // m-tile: rows warpM*16 .. +15
    const int warpN = wid >> 2;    // n-tile within 32-chunk: cols warpN*16 .. +15
    const int base  = blockIdx.x * MT;

    // ============ Phase A: generate h/p/q split tiles (once per CTA) ============
    // element (m,k): byte off = m*512 + (((k>>3)^(m&7))<<4) + (k&7)*2
    {
        const int gm  = tid >> 2;            // 0..63
        const int gk0 = (tid & 3) * 64;      // k range start
        const float t = __ldg(&t_in[base + gm]);
        const float x = fmaf(t, 0.1f, -1.0f);
        #pragma unroll 4
        for (int kk = 0; kk < 64; kk += 2) {
            const int k = gk0 + kk;
            float hv[2], pv[2], qv[2];
            #pragma unroll
            for (int e = 0; e < 2; e++) {
                const float w = __ldg(&W0[k + e]);
                const float d = 0.1f * w;
                const float z = fmaf(x, w, __ldg(&b0[k + e]));
                const float h = tanh_fast(z);
                const float u = 1.0f - h * h;
                hv[e] = h; pv[e] = u * d; qv[e] = -2.0f * h * u * d * d;
            }
            const uint32_t off = (uint32_t)(gm * 512 + ((((k >> 3) ^ (gm & 7))) << 4) + (k & 7) * 2);
            float h0 = bhi(hv[0]), h1 = bhi(hv[1]);
            *(uint32_t*)(smc + A_T(0,0) + off) = pk(h0, h1);
            *(uint32_t*)(smc + A_T(0,1) + off) = pk(hv[0] - h0, hv[1] - h1);
            h0 = bhi(pv[0]); h1 = bhi(pv[1]);
            *(uint32_t*)(smc + A_T(1,0) + off) = pk(h0, h1);
            *(uint32_t*)(smc + A_T(1,1) + off) = pk(pv[0] - h0, pv[1] - h1);
            h0 = bhi(qv[0]); h1 = bhi(qv[1]);
            *(uint32_t*)(smc + A_T(2,0) + off) = pk(h0, h1);
            *(uint32_t*)(smc + A_T(2,1) + off) = pk(qv[0] - h0, qv[1] - h1);
        }
    }

    // per-thread ldmatrix address components (canonical x4: lanes 0-15 rows, 16-31 k-half)
    const int l16 = lane & 15;
    const int csel = lane >> 4;
    const uint32_t xr   = (uint32_t)(l16 & 7);
    const uint32_t rowA = (uint32_t)((warpM * 16 + l16) * 512);
    const uint32_t rowB = (uint32_t)((warpN * 16 + l16) * 512);
    const int q  = lane & 3;       // C/A-frag col-pair & B-frag k-pair
    const int br = lane >> 2;      // C/A-frag row & B-frag n

    // layer-2 accumulators: out/out_t/out_tt [16m x 32bus] per warp (partial over k2)
    float acc2[3][4][4];
    #pragma unroll
    for (int s = 0; s < 3; s++)
        #pragma unroll
        for (int nb = 0; nb < 4; nb++)
            #pragma unroll
            for (int e = 0; e < 4; e++) acc2[s][nb][e] = 0.0f;

    // ============ main loop over 8 n-chunks of 32 columns ============
    for (int c = 0; c < NCH; c++) {
        __syncthreads();   // prior chunk's B1 reads (and phase-A writes) complete

        // ---- load W1^T chunk: [32 n][256 k] bf16 hi/lo ----
        {
            const int n = tid & 31;
            #pragma unroll 4
            for (int i = 0; i < 16; i++) {
                const int kp = (tid >> 5) + i * 8;
                const int k  = kp * 2;
                const float v0 = __ldg(&W1[(size_t)k * HD + c * 32 + n]);
                const float v1 = __ldg(&W1[(size_t)(k + 1) * HD + c * 32 + n]);
                const float h0 = bhi(v0), h1 = bhi(v1);
                const uint32_t off = (uint32_t)(n * 512 + ((((k >> 3) ^ (n & 7))) << 4) + (k & 7) * 2);
                *(uint32_t*)(smc + B1_T(0) + off) = pk(h0, h1);
                *(uint32_t*)(smc + B1_T(1) + off) = pk(v0 - h0, v1 - h1);
            }
        }
        __syncthreads();

        // ---- layer-1: z/zp/zq [16m x 16n] per warp, K = 256 ----
        float acc[3][2][4];
        #pragma unroll
        for (int s = 0; s < 3; s++)
            #pragma unroll
            for (int t = 0; t < 2; t++)
                #pragma unroll
                for (int e = 0; e < 4; e++) acc[s][t][e] = 0.0f;

        #pragma unroll 4
        for (int kt = 0; kt < 16; kt++) {
            const uint32_t co = (uint32_t)((((kt * 2 + csel)) ^ xr) << 4);
            uint32_t ah[3][4], al[3][4], bh[4], bl[4];
            #pragma unroll
            for (int s = 0; s < 3; s++) {
                ldsm4(ah[s], sb + A_T(s,0) + rowA + co);
                ldsm4(al[s], sb + A_T(s,1) + rowA + co);
            }
            ldsm4(bh, sb + B1_T(0) + rowB + co);
            ldsm4(bl, sb + B1_T(1) + rowB + co);
            #pragma unroll
            for (int s = 0; s < 3; s++) {
                #pragma unroll
                for (int t = 0; t < 2; t++) {
                    mma16816(acc[s][t], ah[s], bh[t], bh[t + 2]);
                    mma16816(acc[s][t], al[s], bh[t], bh[t + 2]);
                    mma16816(acc[s][t], ah[s], bl[t], bl[t + 2]);
                }
            }
        }

        // ---- in-register epilogue: bias + tanh chain -> G fragments ----
        const int jg = c * 32 + warpN * 16;   // this warp's 16 j-columns (k2 tile)
        float vg[2][4], vp[2][4], vq[2][4];
        #pragma unroll
        for (int t = 0; t < 2; t++) {
            const float b1a = __ldg(&b1[jg + t * 8 + 2 * q]);
            const float b1b = __ldg(&b1[jg + t * 8 + 2 * q + 1]);
            #pragma unroll
            for (int e = 0; e < 4; e++) {
                const float zh = acc[0][t][e] + ((e & 1) ? b1b : b1a);
                const float zp = acc[1][t][e];
                const float zq = acc[2][t][e];
                const float g  = tanh_fast(zh);
                const float u  = 1.0f - g * g;
                vg[t][e] = g;
                vp[t][e] = u * zp;
                vq[t][e] = u * fmaf(-2.0f * g * zp, zp, zq);
            }
        }

        // ---- layer-2: C2 += G(k2=16) @ W2 ; A-frags direct from C-frags ----
        uint32_t w2h[4][2], w2l[4][2];
        #pragma unroll
        for (int nb = 0; nb < 4; nb++) {
            const int bus = nb * 8 + br;
            const float v0 = __ldg(&W2[(size_t)(jg + 2 * q)     * NBUS + bus]);
            const float v1 = __ldg(&W2[(size_t)(jg + 2 * q + 1) * NBUS + bus]);
            const float v2 = __ldg(&W2[(size_t)(jg + 2 * q + 8) * NBUS + bus]);
            const float v3 = __ldg(&W2[(size_t)(jg + 2 * q + 9) * NBUS + bus]);
            const float h0 = bhi(v0), h1 = bhi(v1), h2 = bhi(v2), h3 = bhi(v3);
            w2h[nb][0] = pk(h0, h1);          w2h[nb][1] = pk(h2, h3);
            w2l[nb][0] = pk(v0 - h0, v1 - h1); w2l[nb][1] = pk(v2 - h2, v3 - h3);
        }
        #pragma unroll
        for (int s = 0; s < 3; s++) {
            const float (*v)[4] = (s == 0) ? vg : (s == 1) ? vp : vq;
            uint32_t a2h[4], a2l[4];
            // a0={(r,k01) t0 c01}, a1={t0 c23}, a2={t1 c01}, a3={t1 c23}
            float x0 = bhi(v[0][0]), x1 = bhi(v[0][1]);
            a2h[0] = pk(x0, x1); a2l[0] = pk(v[0][0] - x0, v[0][1] - x1);
            x0 = bhi(v[0][2]); x1 = bhi(v[0][3]);
            a2h[1] = pk(x0, x1); a2l[1] = pk(v[0][2] - x0, v[0][3] - x1);
            x0 = bhi(v[1][0]); x1 = bhi(v[1][1]);
            a2h[2] = pk(x0, x1); a2l[2] = pk(v[1][0] - x0, v[1][1] - x1);
            x0 = bhi(v[1][2]); x1 = bhi(v[1][3]);
            a2h[3] = pk(x0, x1); a2l[3] = pk(v[1][2] - x0, v[1][3] - x1);
            #pragma unroll
            for (int nb = 0; nb < 4; nb++) {
                mma16816(acc2[s][nb], a2h, w2h[nb][0], w2h[nb][1]);
                mma16816(acc2[s][nb], a2l, w2h[nb][0], w2h[nb][1]);
                mma16816(acc2[s][nb], a2h, w2l[nb][0], w2l[nb][1]);
            }
        }
    }

    // ============ cross-warp k2 reduction + physics ============
    __syncthreads();   // all A/B1 smem reads done -> safe to alias
    float* f_o   = (float*)(smc + O_OFF);
    float* f_ot  = (float*)(smc + OT_OFF);
    float* f_ott = (float*)(smc + OTT_OFF);
    float* scs   = (float*)(smc + SCS_OFF);
    float* scc   = (float*)(smc + SCC_OFF);

    if (warpN == 0) {
        #pragma unroll
        for (int s = 0; s < 3; s++) {
            float* dst = (s == 0) ? f_o : (s == 1) ? f_ot : f_ott;
            #pragma unroll
            for (int nb = 0; nb < 4; nb++)
                #pragma unroll
                for (int e = 0; e < 4; e++) {
                    const int row = warpM * 16 + br + ((e >> 1) << 3);
                    const int bus = nb * 8 + 2 * q + (e & 1);
                    dst[row * NBUS + bus] = acc2[s][nb][e];
                }
        }
    }
    __syncthreads();
    if (warpN == 1) {
        #pragma unroll
        for (int s = 0; s < 3; s++) {
            float* dst = (s == 0) ? f_o : (s == 1) ? f_ot : f_ott;
            #pragma unroll
            for (int nb = 0; nb < 4; nb++)
                #pragma unroll
                for (int e = 0; e < 4; e++) {
                    const int row = warpM * 16 + br + ((e >> 1) << 3);
                    const int bus = nb * 8 + 2 * q + (e & 1);
                    float v = dst[row * NBUS + bus] + acc2[s][nb][e];
                    if (s == 0) v += __ldg(&b2[bus]);
                    dst[row * NBUS + bus] = v;
                }
        }
    }
    __syncthreads();

    // sin/cos tables
    #pragma unroll
    for (int i = 0; i < 8; i++) {
        const int cell = tid * 8 + i;
        const int m = cell >> 5, bus = cell & 31;
        float sv, cv;
        __sincosf(f_o[cell], &sv, &cv);
        scs[m * 33 + bus] = sv;
        scc[m * 33 + bus] = cv;
    }
    __syncthreads();

    // physics: thread -> sample pm, buses pb..pb+7
    const int pm = tid >> 2;
    const int pb = (tid & 3) * 8;
    #pragma unroll
    for (int g4 = 0; g4 < 2; g4++) {
        float4 vo, vt, vp4;
        float* po = &vo.x; float* pt = &vt.x; float* pp = &vp4.x;
        const float4 pw = __ldg((const float4*)(power + (size_t)(base + pm) * NBUS + pb + g4 * 4));
        const float* ppw = &pw.x;
        #pragma unroll
        for (int e = 0; e < 4; e++) {
            const int bus = pb + g4 * 4 + e;
            const float o   = f_o  [pm * NBUS + bus];
            const float ot  = f_ot [pm * NBUS + bus];
            const float ott = f_ott[pm * NBUS + bus];
            float accC = 0.0f, accS = 0.0f;
            #pragma unroll
            for (int j = 0; j < NBUS; j++) {
                const float bl2 = __ldg(&lam_b[bus * NBUS + j]);
                accC = fmaf(bl2, scc[pm * 33 + j], accC);
                accS = fmaf(bl2, scs[pm * 33 + j], accS);
            }
            const float conn = scs[pm * 33 + bus] * accC - scc[pm * 33 + bus] * accS;
            const float lm = __ldg(&lam_m[bus]) * __ldg(&bwi[bus]);
            const float ld = __ldg(&lam_d[bus]);
            po[e] = o;
            pt[e] = ot;
            pp[e] = fmaf(lm, ott, fmaf(ld, ot, conn - ppw[e]));
        }
        const size_t gi = (size_t)(base + pm) * NBUS + pb + g4 * 4;
        *(float4*)(out_d  + gi) = vo;
        *(float4*)(out_dt + gi) = vt;
        *(float4*)(out_ph + gi) = vp4;
    }
}

extern "C" void kernel_launch(void* const* d_in, const int* in_sizes, int n_in,
                              void* d_out, int out_size) {
    const float* t_in  = (const float*)d_in[0];
    const float* power = (const float*)d_in[1];
    const float* W0    = (const float*)d_in[2];
    const float* b0    = (const float*)d_in[3];
    const float* W1    = (const float*)d_in[4];
    const float* b1    = (const float*)d_in[5];
    const float* W2    = (const float*)d_in[6];
    const float* b2    = (const float*)d_in[7];
    const float* lam_m = (const float*)d_in[8];
    const float* lam_d = (const float*)d_in[9];
    const float* lam_b = (const float*)d_in[10];
    const float* bwi   = (const float*)d_in[11];

    float* out  = (float*)d_out;
    float* outt = out  + (size_t)NS * NBUS;
    float* outp = outt + (size_t)NS * NBUS;

    cudaFuncSetAttribute(pinn_hmma_kernel, cudaFuncAttributeMaxDynamicSharedMemorySize, SMEM_TOTAL);
    pinn_hmma_kernel<<<NCTA, THREADS, SMEM_TOTAL>>>(t_in, power, W0, b0, W1, b1, W2, b2,
                                                    lam_m, lam_d, lam_b, bwi,
                                                    out, outt, outp);
}

// round 8
// speedup vs baseline: 2.1734x; 1.1641x over previous
#include <cuda_runtime.h>
#include <cuda_bf16.h>
#include <math.h>
#include <stdint.h>

#define NS      65536
#define NBUS    32
#define HD      256
#define MT      64            // samples per CTA
#define NCTA    (NS / MT)
#define THREADS 256
#define NCH     8             // n-chunks of 32 over HD=256

// ---- smem map (dynamic, 229376 B total) ----
// A tiles: 3 streams (h,p,q) x hi/lo, each [64 m][256 k] bf16 = 32768 B
#define A_T(s,hl) (((s)*2+(hl))*32768)
#define B1_T(hl)  (196608 + (hl)*16384)   // W1^T chunk [32 n][256 k] bf16 hi/lo
#define SMEM_TOTAL 229376
// final-phase aliases (A region is dead by then)
#define O_OFF   0             // out      [64][32] f32
#define OT_OFF  8192          // out_t    [64][32] f32
#define OTT_OFF 16384         // out_tt   [64][32] f32
#define SCS_OFF 24576         // sin      [64][33] f32
#define SCC_OFF 33024         // cos      [64][33] f32

// ---- precomputed weight images (device globals; written by prep kernel) ----
// W1 split, stored as the per-chunk swizzled smem image: [chunk 8][32768 B]
__device__ __align__(16) unsigned char g_w1h[NCH * 32768];
__device__ __align__(16) unsigned char g_w1l[NCH * 32768];
// W2 split, pre-packed as MMA B-fragment words: [j/2 128][bus 32] bf16x2
__device__ uint32_t g_w2hp[128 * NBUS];
__device__ uint32_t g_w2lp[128 * NBUS];

static __device__ __forceinline__ uint32_t s2u(const void* p) {
    uint32_t a;
    asm("{ .reg .u64 t; cvta.to.shared.u64 t, %1; cvt.u32.u64 %0, t; }" : "=r"(a) : "l"(p));
    return a;
}
static __device__ __forceinline__ uint32_t pk(float a, float b) {
    __nv_bfloat162 t = __floats2bfloat162_rn(a, b);
    return *reinterpret_cast<uint32_t*>(&t);
}
static __device__ __forceinline__ float bhi(float v) {
    return __bfloat162float(__float2bfloat16(v));
}
static __device__ __forceinline__ float tanh_fast(float x) {
    return 1.0f - __fdividef(2.0f, __expf(2.0f * x) + 1.0f);
}
static __device__ __forceinline__ void ldsm4(uint32_t* r, uint32_t a) {
    asm volatile("ldmatrix.sync.aligned.m8n8.x4.shared.b16 {%0,%1,%2,%3}, [%4];"
                 : "=r"(r[0]), "=r"(r[1]), "=r"(r[2]), "=r"(r[3]) : "r"(a));
}
static __device__ __forceinline__ void mma16816(float* d, const uint32_t* a,
                                                uint32_t b0, uint32_t b1) {
    asm volatile(
        "mma.sync.aligned.m16n8k16.row.col.f32.bf16.bf16.f32 "
        "{%0,%1,%2,%3}, {%4,%5,%6,%7}, {%8,%9}, {%0,%1,%2,%3};"
        : "+f"(d[0]), "+f"(d[1]), "+f"(d[2]), "+f"(d[3])
        : "r"(a[0]), "r"(a[1]), "r"(a[2]), "r"(a[3]), "r"(b0), "r"(b1));
}
static __device__ __forceinline__ void cpa16(uint32_t dst, const void* src) {
    asm volatile("cp.async.cg.shared.global [%0], [%1], 16;"
                 :: "r"(dst), "l"(__cvta_generic_to_global(src)) : "memory");
}

// ============ prep kernel: split + relayout W1 and W2 (same every call) ============
__global__ void prep_kernel(const float* __restrict__ W1, const float* __restrict__ W2) {
    const int idx = blockIdx.x * blockDim.x + threadIdx.x;   // 8192 threads
    if (idx < 8192) {
        // one thread handles 8 consecutive k for one column j = cn
        const int cn = idx >> 5;            // j = 0..255
        const int k8 = idx & 31;            // k octet
        const int c  = cn >> 5, n = cn & 31;
        const uint32_t off = (uint32_t)(c * 32768 + n * 512 + ((k8 ^ (n & 7)) << 4));
        __nv_bfloat16 hv[8], lv[8];
        #pragma unroll
        for (int e = 0; e < 8; e++) {
            const float v = W1[(size_t)(k8 * 8 + e) * HD + cn];
            const float h = bhi(v);
            hv[e] = __float2bfloat16(h);
            lv[e] = __float2bfloat16(v - h);
        }
        *(uint4*)(g_w1h + off) = *(const uint4*)hv;
        *(uint4*)(g_w1l + off) = *(const uint4*)lv;
    }
    if (idx < 128 * NBUS) {
        const int p = idx >> 5, bus = idx & 31;       // j pair (2p, 2p+1)
        const float v0 = W2[(size_t)(2 * p)     * NBUS + bus];
        const float v1 = W2[(size_t)(2 * p + 1) * NBUS + bus];
        const float h0 = bhi(v0), h1 = bhi(v1);
        g_w2hp[idx] = pk(h0, h1);
        g_w2lp[idx] = pk(v0 - h0, v1 - h1);
    }
}

__global__ void __launch_bounds__(THREADS, 1) pinn_hmma_kernel(
    const float* __restrict__ t_in, const float* __restrict__ power,
    const float* __restrict__ W0, const float* __restrict__ b0,
    const float* __restrict__ b1, const float* __restrict__ b2,
    const float* __restrict__ lam_m, const float* __restrict__ lam_d,
    const float* __restrict__ lam_b, const float* __restrict__ bwi,
    float* __restrict__ out_d, float* __restrict__ out_dt, float* __restrict__ out_ph)
{
    extern __shared__ __align__(1024) char smc[];
    const uint32_t sb = s2u(smc);

    const int tid   = threadIdx.x;
    const int lane  = tid & 31;
    const int wid   = tid >> 5;
    const int warpM = wid & 3;     // m-tile: rows warpM*16 .. +15
    const int warpN = wid >> 2;    // n-tile within 32-chunk: cols warpN*16 .. +15
    const int base  = blockIdx.x * MT;

    // ============ Phase A: generate h/p/q split tiles (once per CTA) ============
    {
        const int gm  = tid >> 2;            // 0..63
        const int gk0 = (tid & 3) * 64;      // k range start
        const float t = __ldg(&t_in[base + gm]);
        const float x = fmaf(t, 0.1f, -1.0f);
        #pragma unroll 4
        for (int kk = 0; kk < 64; kk += 2) {
            const int k = gk0 + kk;
            float hv[2], pv[2], qv[2];
            #pragma unroll
            for (int e = 0; e < 2; e++) {
                const float w = __ldg(&W0[k + e]);
                const float d = 0.1f * w;
                const float z = fmaf(x, w, __ldg(&b0[k + e]));
                const float h = tanh_fast(z);
                const float u = 1.0f - h * h;
                hv[e] = h; pv[e] = u * d; qv[e] = -2.0f * h * u * d * d;
            }
            const uint32_t off = (uint32_t)(gm * 512 + ((((k >> 3) ^ (gm & 7))) << 4) + (k & 7) * 2);
            float h0 = bhi(hv[0]), h1 = bhi(hv[1]);
            *(uint32_t*)(smc + A_T(0,0) + off) = pk(h0, h1);
            *(uint32_t*)(smc + A_T(0,1) + off) = pk(hv[0] - h0, hv[1] - h1);
            h0 = bhi(pv[0]); h1 = bhi(pv[1]);
            *(uint32_t*)(smc + A_T(1,0) + off) = pk(h0, h1);
            *(uint32_t*)(smc + A_T(1,1) + off) = pk(pv[0] - h0, pv[1] - h1);
            h0 = bhi(qv[0]); h1 = bhi(qv[1]);
            *(uint32_t*)(smc + A_T(2,0) + off) = pk(h0, h1);
            *(uint32_t*)(smc + A_T(2,1) + off) = pk(qv[0] - h0, qv[1] - h1);
        }
    }

    // per-thread ldmatrix address components (canonical x4: lanes 0-15 rows, 16-31 k-half)
    const int l16 = lane & 15;
    const int csel = lane >> 4;
    const uint32_t xr   = (uint32_t)(l16 & 7);
    const uint32_t rowA = (uint32_t)((warpM * 16 + l16) * 512);
    const uint32_t rowB = (uint32_t)((warpN * 16 + l16) * 512);
    const int q  = lane & 3;       // C/A-frag col-pair & B-frag k-pair
    const int br = lane >> 2;      // C/A-frag row & B-frag n

    // layer-2 accumulators: out/out_t/out_tt [16m x 32bus] per warp (partial over k2)
    float acc2[3][4][4];
    #pragma unroll
    for (int s = 0; s < 3; s++)
        #pragma unroll
        for (int nb = 0; nb < 4; nb++)
            #pragma unroll
            for (int e = 0; e < 4; e++) acc2[s][nb][e] = 0.0f;

    // ============ main loop over 8 n-chunks of 32 columns ============
    for (int c = 0; c < NCH; c++) {
        __syncthreads();   // prior chunk's B1 reads (and phase-A writes) complete

        // ---- B1 chunk: straight async copy of the precomputed swizzled image ----
        {
            const unsigned char* srcH = g_w1h + c * 32768;
            const unsigned char* srcL = g_w1l + c * 32768;
            const uint32_t dH = sb + B1_T(0) + tid * 16;
            const uint32_t dL = sb + B1_T(1) + tid * 16;
            #pragma unroll
            for (int i = 0; i < 4; i++) {
                cpa16(dH + i * 4096, srcH + tid * 16 + i * 4096);
                cpa16(dL + i * 4096, srcL + tid * 16 + i * 4096);
            }
            asm volatile("cp.async.commit_group;");
            asm volatile("cp.async.wait_group 0;" ::: "memory");
        }
        __syncthreads();

        // ---- layer-1: z/zp/zq [16m x 16n] per warp, K = 256 ----
        float acc[3][2][4];
        #pragma unroll
        for (int s = 0; s < 3; s++)
            #pragma unroll
            for (int t = 0; t < 2; t++)
                #pragma unroll
                for (int e = 0; e < 4; e++) acc[s][t][e] = 0.0f;

        #pragma unroll 4
        for (int kt = 0; kt < 16; kt++) {
            const uint32_t co = (uint32_t)((((kt * 2 + csel)) ^ xr) << 4);
            uint32_t ah[3][4], al[3][4], bh[4], bl[4];
            #pragma unroll
            for (int s = 0; s < 3; s++) {
                ldsm4(ah[s], sb + A_T(s,0) + rowA + co);
                ldsm4(al[s], sb + A_T(s,1) + rowA + co);
            }
            ldsm4(bh, sb + B1_T(0) + rowB + co);
            ldsm4(bl, sb + B1_T(1) + rowB + co);
            #pragma unroll
            for (int s = 0; s < 3; s++) {
                #pragma unroll
                for (int t = 0; t < 2; t++) {
                    mma16816(acc[s][t], ah[s], bh[t], bh[t + 2]);
                    mma16816(acc[s][t], al[s], bh[t], bh[t + 2]);
                    mma16816(acc[s][t], ah[s], bl[t], bl[t + 2]);
                }
            }
        }

        // ---- in-register epilogue: bias + tanh chain -> G fragments ----
        const int jg = c * 32 + warpN * 16;   // this warp's 16 j-columns (k2 tile)
        float vg[2][4], vp[2][4], vq[2][4];
        #pragma unroll
        for (int t = 0; t < 2; t++) {
            const float b1a = __ldg(&b1[jg + t * 8 + 2 * q]);
            const float b1b = __ldg(&b1[jg + t * 8 + 2 * q + 1]);
            #pragma unroll
            for (int e = 0; e < 4; e++) {
                const float zh = acc[0][t][e] + ((e & 1) ? b1b : b1a);
                const float zp = acc[1][t][e];
                const float zq = acc[2][t][e];
                const float g  = tanh_fast(zh);
                const float u  = 1.0f - g * g;
                vg[t][e] = g;
                vp[t][e] = u * zp;
                vq[t][e] = u * fmaf(-2.0f * g * zp, zp, zq);
            }
        }

        // ---- layer-2: C2 += G(k2=16) @ W2 ; W2 frags precomputed ----
        uint32_t w2h[4][2], w2l[4][2];
        {
            const int p0 = (jg + 2 * q) >> 1;        // j pair index (even j)
            const int p1 = (jg + 2 * q + 8) >> 1;
            #pragma unroll
            for (int nb = 0; nb < 4; nb++) {
                const int bus = nb * 8 + br;
                w2h[nb][0] = __ldg(&g_w2hp[p0 * NBUS + bus]);
                w2h[nb][1] = __ldg(&g_w2hp[p1 * NBUS + bus]);
                w2l[nb][0] = __ldg(&g_w2lp[p0 * NBUS + bus]);
                w2l[nb][1] = __ldg(&g_w2lp[p1 * NBUS + bus]);
            }
        }
        #pragma unroll
        for (int s = 0; s < 3; s++) {
            const float (*v)[4] = (s == 0) ? vg : (s == 1) ? vp : vq;
            uint32_t a2h[4], a2l[4];
            float x0 = bhi(v[0][0]), x1 = bhi(v[0][1]);
            a2h[0] = pk(x0, x1); a2l[0] = pk(v[0][0] - x0, v[0][1] - x1);
            x0 = bhi(v[0][2]); x1 = bhi(v[0][3]);
            a2h[1] = pk(x0, x1); a2l[1] = pk(v[0][2] - x0, v[0][3] - x1);
            x0 = bhi(v[1][0]); x1 = bhi(v[1][1]);
            a2h[2] = pk(x0, x1); a2l[2] = pk(v[1][0] - x0, v[1][1] - x1);
            x0 = bhi(v[1][2]); x1 = bhi(v[1][3]);
            a2h[3] = pk(x0, x1); a2l[3] = pk(v[1][2] - x0, v[1][3] - x1);
            #pragma unroll
            for (int nb = 0; nb < 4; nb++) {
                mma16816(acc2[s][nb], a2h, w2h[nb][0], w2h[nb][1]);
                mma16816(acc2[s][nb], a2l, w2h[nb][0], w2h[nb][1]);
                mma16816(acc2[s][nb], a2h, w2l[nb][0], w2l[nb][1]);
            }
        }
    }

    // ============ cross-warp k2 reduction + physics ============
    __syncthreads();   // all A/B1 smem reads done -> safe to alias
    float* f_o   = (float*)(smc + O_OFF);
    float* f_ot  = (float*)(smc + OT_OFF);
    float* f_ott = (float*)(smc + OTT_OFF);
    float* scs   = (float*)(smc + SCS_OFF);
    float* scc   = (float*)(smc + SCC_OFF);

    if (warpN == 0) {
        #pragma unroll
        for (int s = 0; s < 3; s++) {
            float* dst = (s == 0) ? f_o : (s == 1) ? f_ot : f_ott;
            #pragma unroll
            for (int nb = 0; nb < 4; nb++)
                #pragma unroll
                for (int e = 0; e < 4; e++) {
                    const int row = warpM * 16 + br + ((e >> 1) << 3);
                    const int bus = nb * 8 + 2 * q + (e & 1);
                    dst[row * NBUS + bus] = acc2[s][nb][e];
                }
        }
    }
    __syncthreads();
    if (warpN == 1) {
        #pragma unroll
        for (int s = 0; s < 3; s++) {
            float* dst = (s == 0) ? f_o : (s == 1) ? f_ot : f_ott;
            #pragma unroll
            for (int nb = 0; nb < 4; nb++)
                #pragma unroll
                for (int e = 0; e < 4; e++) {
                    const int row = warpM * 16 + br + ((e >> 1) << 3);
                    const int bus = nb * 8 + 2 * q + (e & 1);
                    float v = dst[row * NBUS + bus] + acc2[s][nb][e];
                    if (s == 0) v += __ldg(&b2[bus]);
                    dst[row * NBUS + bus] = v;
                }
        }
    }
    __syncthreads();

    // sin/cos tables
    #pragma unroll
    for (int i = 0; i < 8; i++) {
        const int cell = tid * 8 + i;
        const int m = cell >> 5, bus = cell & 31;
        float sv, cv;
        __sincosf(f_o[cell], &sv, &cv);
        scs[m * 33 + bus] = sv;
        scc[m * 33 + bus] = cv;
    }
    __syncthreads();

    // physics: thread -> sample pm, buses pb..pb+7
    const int pm = tid >> 2;
    const int pb = (tid & 3) * 8;
    #pragma unroll
    for (int g4 = 0; g4 < 2; g4++) {
        float4 vo, vt, vp4;
        float* po = &vo.x; float* pt = &vt.x; float* pp = &vp4.x;
        const float4 pw = __ldg((const float4*)(power + (size_t)(base + pm) * NBUS + pb + g4 * 4));
        const float* ppw = &pw.x;
        #pragma unroll
        for (int e = 0; e < 4; e++) {
            const int bus = pb + g4 * 4 + e;
            const float o   = f_o  [pm * NBUS + bus];
            const float ot  = f_ot [pm * NBUS + bus];
            const float ott = f_ott[pm * NBUS + bus];
            float accC = 0.0f, accS = 0.0f;
            #pragma unroll
            for (int j = 0; j < NBUS; j++) {
                const float bl2 = __ldg(&lam_b[bus * NBUS + j]);
                accC = fmaf(bl2, scc[pm * 33 + j], accC);
                accS = fmaf(bl2, scs[pm * 33 + j], accS);
            }
            const float conn = scs[pm * 33 + bus] * accC - scc[pm * 33 + bus] * accS;
            const float lm = __ldg(&lam_m[bus]) * __ldg(&bwi[bus]);
            const float ld = __ldg(&lam_d[bus]);
            po[e] = o;
            pt[e] = ot;
            pp[e] = fmaf(lm, ott, fmaf(ld, ot, conn - ppw[e]));
        }
        const size_t gi = (size_t)(base + pm) * NBUS + pb + g4 * 4;
        *(float4*)(out_d  + gi) = vo;
        *(float4*)(out_dt + gi) = vt;
        *(float4*)(out_ph + gi) = vp4;
    }
}

extern "C" void kernel_launch(void* const* d_in, const int* in_sizes, int n_in,
                              void* d_out, int out_size) {
    const float* t_in  = (const float*)d_in[0];
    const float* power = (const float*)d_in[1];
    const float* W0    = (const float*)d_in[2];
    const float* b0    = (const float*)d_in[3];
    const float* W1    = (const float*)d_in[4];
    const float* b1    = (const float*)d_in[5];
    const float* W2    = (const float*)d_in[6];
    const float* b2    = (const float*)d_in[7];
    const float* lam_m = (const float*)d_in[8];
    const float* lam_d = (const float*)d_in[9];
    const float* lam_b = (const float*)d_in[10];
    const float* bwi   = (const float*)d_in[11];

    float* out  = (float*)d_out;
    float* outt = out  + (size_t)NS * NBUS;
    float* outp = outt + (size_t)NS * NBUS;

    prep_kernel<<<32, 256>>>(W1, W2);

    cudaFuncSetAttribute(pinn_hmma_kernel, cudaFuncAttributeMaxDynamicSharedMemorySize, SMEM_TOTAL);
    pinn_hmma_kernel<<<NCTA, THREADS, SMEM_TOTAL>>>(t_in, power, W0, b0, b1, b2,
                                                    lam_m, lam_d, lam_b, bwi,
                                                    out, outt, outp);
}

// round 10
// speedup vs baseline: 4.3264x; 1.9906x over previous
#include <cuda_runtime.h>
#include <cuda_fp16.h>
#include <math.h>
#include <stdint.h>

#define NS      65536
#define NBUS    32
#define HD      256
#define MT      64            // samples per CTA
#define NCTA    (NS / MT)
#define THREADS 256
#define NCH     8             // n-chunks of 32 over HD=256

// ---- smem map (dynamic, 114688 B total -> 2 CTAs/SM) ----
// A tiles: 3 streams (h,p,q), each [64 m][256 k] fp16 = 32768 B
#define A_T(s)  ((s)*32768)
#define B1_T    98304                     // W1^T chunk [32 n][256 k] fp16
#define SMEM_TOTAL 114688
// final-phase aliases (A region is dead by then)
#define O_OFF   0             // out      [64][32] f32
#define OT_OFF  8192          // out_t    [64][32] f32
#define OTT_OFF 16384         // out_tt   [64][32] f32
#define SCS_OFF 24576         // sin      [64][33] f32
#define SCC_OFF 33024         // cos      [64][33] f32

// ---- precomputed weight images (device globals; written by prep kernel) ----
// W1 fp16, stored as the per-chunk swizzled smem image: [chunk 8][16384 B]
__device__ __align__(16) unsigned char g_w1p[NCH * 16384];
// W2 fp16, pre-packed as MMA B-fragment words: [j/2 128][bus 32] half2
__device__ uint32_t g_w2p[128 * NBUS];

static __device__ __forceinline__ uint32_t s2u(const void* p) {
    uint32_t a;
    asm("{ .reg .u64 t; cvta.to.shared.u64 t, %1; cvt.u32.u64 %0, t; }" : "=r"(a) : "l"(p));
    return a;
}
static __device__ __forceinline__ uint32_t pkh(float a, float b) {
    __half2 t = __floats2half2_rn(a, b);
    return *reinterpret_cast<uint32_t*>(&t);
}
static __device__ __forceinline__ float tanh_fast(float x) {
    return 1.0f - __fdividef(2.0f, __expf(2.0f * x) + 1.0f);
}
static __device__ __forceinline__ void ldsm4(uint32_t* r, uint32_t a) {
    asm volatile("ldmatrix.sync.aligned.m8n8.x4.shared.b16 {%0,%1,%2,%3}, [%4];"
                 : "=r"(r[0]), "=r"(r[1]), "=r"(r[2]), "=r"(r[3]) : "r"(a));
}
static __device__ __forceinline__ void mma16816(float* d, const uint32_t* a,
                                                uint32_t b0, uint32_t b1) {
    asm volatile(
        "mma.sync.aligned.m16n8k16.row.col.f32.f16.f16.f32 "
        "{%0,%1,%2,%3}, {%4,%5,%6,%7}, {%8,%9}, {%0,%1,%2,%3};"
        : "+f"(d[0]), "+f"(d[1]), "+f"(d[2]), "+f"(d[3])
        : "r"(a[0]), "r"(a[1]), "r"(a[2]), "r"(a[3]), "r"(b0), "r"(b1));
}
static __device__ __forceinline__ void cpa16(uint32_t dst, const void* src) {
    asm volatile("cp.async.cg.shared.global [%0], [%1], 16;"
                 :: "r"(dst), "l"(__cvta_generic_to_global(src)) : "memory");
}

// ============ prep kernel: convert + relayout W1 / W2 to fp16 images ============
__global__ void prep_kernel(const float* __restrict__ W1, const float* __restrict__ W2) {
    const int idx = blockIdx.x * blockDim.x + threadIdx.x;   // 8192 threads
    if (idx < 8192) {
        const int cn = idx >> 5;            // column j = 0..255
        const int k8 = idx & 31;            // k octet
        const int c  = cn >> 5, n = cn & 31;
        const uint32_t off = (uint32_t)(c * 16384 + n * 512 + ((k8 ^ (n & 7)) << 4));
        __half hv[8];
        #pragma unroll
        for (int e = 0; e < 8; e++)
            hv[e] = __float2half_rn(W1[(size_t)(k8 * 8 + e) * HD + cn]);
        *(uint4*)(g_w1p + off) = *(const uint4*)hv;
    }
    if (idx < 128 * NBUS) {
        const int p = idx >> 5, bus = idx & 31;       // j pair (2p, 2p+1)
        g_w2p[idx] = pkh(W2[(size_t)(2 * p) * NBUS + bus],
                         W2[(size_t)(2 * p + 1) * NBUS + bus]);
    }
}

__global__ void __launch_bounds__(THREADS, 2) pinn_hmma_kernel(
    const float* __restrict__ t_in, const float* __restrict__ power,
    const float* __restrict__ W0, const float* __restrict__ b0,
    const float* __restrict__ b1, const float* __restrict__ b2,
    const float* __restrict__ lam_m, const float* __restrict__ lam_d,
    const float* __restrict__ lam_b, const float* __restrict__ bwi,
    float* __restrict__ out_d, float* __restrict__ out_dt, float* __restrict__ out_ph)
{
    extern __shared__ __align__(1024) char smc[];
    const uint32_t sb = s2u(smc);

    const int tid   = threadIdx.x;
    const int lane  = tid & 31;
    const int wid   = tid >> 5;
    const int warpM = wid & 3;     // m-tile: rows warpM*16 .. +15
    const int warpN = wid >> 2;    // n-tile within 32-chunk: cols warpN*16 .. +15
    const int base  = blockIdx.x * MT;

    // ============ Phase A: generate h/p/q fp16 tiles (once per CTA) ============
    // element (m,k): byte off = m*512 + (((k>>3)^(m&7))<<4) + (k&7)*2
    {
        const int gm  = tid >> 2;            // 0..63
        const int gk0 = (tid & 3) * 64;      // k range start
        const float t = __ldg(&t_in[base + gm]);
        const float x = fmaf(t, 0.1f, -1.0f);
        #pragma unroll 4
        for (int kk = 0; kk < 64; kk += 2) {
            const int k = gk0 + kk;
            float hv[2], pv[2], qv[2];
            #pragma unroll
            for (int e = 0; e < 2; e++) {
                const float w = __ldg(&W0[k + e]);
                const float d = 0.1f * w;
                const float z = fmaf(x, w, __ldg(&b0[k + e]));
                const float h = tanh_fast(z);
                const float u = 1.0f - h * h;
                hv[e] = h; pv[e] = u * d; qv[e] = -2.0f * h * u * d * d;
            }
            const uint32_t off = (uint32_t)(gm * 512 + ((((k >> 3) ^ (gm & 7))) << 4) + (k & 7) * 2);
            *(uint32_t*)(smc + A_T(0) + off) = pkh(hv[0], hv[1]);
            *(uint32_t*)(smc + A_T(1) + off) = pkh(pv[0], pv[1]);
            *(uint32_t*)(smc + A_T(2) + off) = pkh(qv[0], qv[1]);
        }
    }

    // per-thread ldmatrix address components (canonical x4: lanes 0-15 rows, 16-31 k-half)
    const int l16 = lane & 15;
    const int csel = lane >> 4;
    const uint32_t xr   = (uint32_t)(l16 & 7);
    const uint32_t rowA = (uint32_t)((warpM * 16 + l16) * 512);
    const uint32_t rowB = (uint32_t)((warpN * 16 + l16) * 512);
    const int q  = lane & 3;       // C/A-frag col-pair & B-frag k-pair
    const int br = lane >> 2;      // C/A-frag row & B-frag n

    // layer-2 accumulators: out/out_t/out_tt [16m x 32bus] per warp (partial over k2)
    float acc2[3][4][4];
    #pragma unroll
    for (int s = 0; s < 3; s++)
        #pragma unroll
        for (int nb = 0; nb < 4; nb++)
            #pragma unroll
            for (int e = 0; e < 4; e++) acc2[s][nb][e] = 0.0f;

    // ============ main loop over 8 n-chunks of 32 columns ============
    for (int c = 0; c < NCH; c++) {
        __syncthreads();   // prior chunk's B1 reads (and phase-A writes) complete

        // ---- B1 chunk: straight async copy of the precomputed swizzled image ----
        {
            const unsigned char* src = g_w1p + c * 16384;
            const uint32_t d0 = sb + B1_T + tid * 16;
            #pragma unroll
            for (int i = 0; i < 4; i++)
                cpa16(d0 + i * 4096, src + tid * 16 + i * 4096);
            asm volatile("cp.async.commit_group;");
            asm volatile("cp.async.wait_group 0;" ::: "memory");
        }
        __syncthreads();

        // ---- layer-1: z/zp/zq [16m x 16n] per warp, K = 256 ----
        float acc[3][2][4];
        #pragma unroll
        for (int s = 0; s < 3; s++)
            #pragma unroll
            for (int t = 0; t < 2; t++)
                #pragma unroll
                for (int e = 0; e < 4; e++) acc[s][t][e] = 0.0f;

        #pragma unroll 8
        for (int kt = 0; kt < 16; kt++) {
            const uint32_t co = (uint32_t)((((kt * 2 + csel)) ^ xr) << 4);
            uint32_t ah[3][4], bh[4];
            #pragma unroll
            for (int s = 0; s < 3; s++)
                ldsm4(ah[s], sb + A_T(s) + rowA + co);
            ldsm4(bh, sb + B1_T + rowB + co);
            #pragma unroll
            for (int s = 0; s < 3; s++)
                #pragma unroll
                for (int t = 0; t < 2; t++)
                    mma16816(acc[s][t], ah[s], bh[t], bh[t + 2]);
        }

        // ---- in-register epilogue: bias + tanh chain -> G fragments ----
        const int jg = c * 32 + warpN * 16;   // this warp's 16 j-columns (k2 tile)
        float vg[2][4], vp[2][4], vq[2][4];
        #pragma unroll
        for (int t = 0; t < 2; t++) {
            const float b1a = __ldg(&b1[jg + t * 8 + 2 * q]);
            const float b1b = __ldg(&b1[jg + t * 8 + 2 * q + 1]);
            #pragma unroll
            for (int e = 0; e < 4; e++) {
                const float zh = acc[0][t][e] + ((e & 1) ? b1b : b1a);
                const float zp = acc[1][t][e];
                const float zq = acc[2][t][e];
                const float g  = tanh_fast(zh);
                const float u  = 1.0f - g * g;
                vg[t][e] = g;
                vp[t][e] = u * zp;
                vq[t][e] = u * fmaf(-2.0f * g * zp, zp, zq);
            }
        }

        // ---- layer-2: C2 += G(k2=16) @ W2 ; W2 frags precomputed fp16 ----
        uint32_t w2f[4][2];
        {
            const int p0 = (jg + 2 * q) >> 1;        // j pair index (even j)
            const int p1 = (jg + 2 * q + 8) >> 1;
            #pragma unroll
            for (int nb = 0; nb < 4; nb++) {
                const int bus = nb * 8 + br;
                w2f[nb][0] = __ldg(&g_w2p[p0 * NBUS + bus]);
                w2f[nb][1] = __ldg(&g_w2p[p1 * NBUS + bus]);
            }
        }
        #pragma unroll
        for (int s = 0; s < 3; s++) {
            const float (*v)[4] = (s == 0) ? vg : (s == 1) ? vp : vq;
            uint32_t a2[4];
            // a0={(r,k01) t0 c01}, a1={t0 c23}, a2={t1 c01}, a3={t1 c23}
            a2[0] = pkh(v[0][0], v[0][1]);
            a2[1] = pkh(v[0][2], v[0][3]);
            a2[2] = pkh(v[1][0], v[1][1]);
            a2[3] = pkh(v[1][2], v[1][3]);
            #pragma unroll
            for (int nb = 0; nb < 4; nb++)
                mma16816(acc2[s][nb], a2, w2f[nb][0], w2f[nb][1]);
        }
    }

    // ============ cross-warp k2 reduction + physics ============
    __syncthreads();   // all A/B1 smem reads done -> safe to alias
    float* f_o   = (float*)(smc + O_OFF);
    float* f_ot  = (float*)(smc + OT_OFF);
    float* f_ott = (float*)(smc + OTT_OFF);
    float* scs   = (float*)(smc + SCS_OFF);
    float* scc   = (float*)(smc + SCC_OFF);

    if (warpN == 0) {
        #pragma unroll
        for (int s = 0; s < 3; s++) {
            float* dst = (s == 0) ? f_o : (s == 1) ? f_ot : f_ott;
            #pragma unroll
            for (int nb = 0; nb < 4; nb++)
                #pragma unroll
                for (int e = 0; e < 4; e++) {
                    const int row = warpM * 16 + br + ((e >> 1) << 3);
                    const int bus = nb * 8 + 2 * q + (e & 1);
                    dst[row * NBUS + bus] = acc2[s][nb][e];
                }
        }
    }
    __syncthreads();
    if (warpN == 1) {
        #pragma unroll
        for (int s = 0; s < 3; s++) {
            float* dst = (s == 0) ? f_o : (s == 1) ? f_ot : f_ott;
            #pragma unroll
            for (int nb = 0; nb < 4; nb++)
                #pragma unroll
                for (int e = 0; e < 4; e++) {
                    const int row = warpM * 16 + br + ((e >> 1) << 3);
                    const int bus = nb * 8 + 2 * q + (e & 1);
                    float v = dst[row * NBUS + bus] + acc2[s][nb][e];
                    if (s == 0) v += __ldg(&b2[bus]);
                    dst[row * NBUS + bus] = v;
                }
        }
    }
    __syncthreads();

    // sin/cos tables
    #pragma unroll
    for (int i = 0; i < 8; i++) {
        const int cell = tid * 8 + i;
        const int m = cell >> 5, bus = cell & 31;
        float sv, cv;
        __sincosf(f_o[cell], &sv, &cv);
        scs[m * 33 + bus] = sv;
        scc[m * 33 + bus] = cv;
    }
    __syncthreads();

    // physics: thread -> sample pm, buses pb..pb+7
    const int pm = tid >> 2;
    const int pb = (tid & 3) * 8;
    #pragma unroll
    for (int g4 = 0; g4 < 2; g4++) {
        float4 vo, vt, vp4;
        float* po = &vo.x; float* pt = &vt.x; float* pp = &vp4.x;
        const float4 pw = __ldg((const float4*)(power + (size_t)(base + pm) * NBUS + pb + g4 * 4));
        const float* ppw = &pw.x;
        #pragma unroll
        for (int e = 0; e < 4; e++) {
            const int bus = pb + g4 * 4 + e;
            const float o   = f_o  [pm * NBUS + bus];
            const float ot  = f_ot [pm * NBUS + bus];
            const float ott = f_ott[pm * NBUS + bus];
            float accC = 0.0f, accS = 0.0f;
            #pragma unroll
            for (int j = 0; j < NBUS; j++) {
                const float bl2 = __ldg(&lam_b[bus * NBUS + j]);
                accC = fmaf(bl2, scc[pm * 33 + j], accC);
                accS = fmaf(bl2, scs[pm * 33 + j], accS);
            }
            const float conn = scs[pm * 33 + bus] * accC - scc[pm * 33 + bus] * accS;
            const float lm = __ldg(&lam_m[bus]) * __ldg(&bwi[bus]);
            const float ld = __ldg(&lam_d[bus]);
            po[e] = o;
            pt[e] = ot;
            pp[e] = fmaf(lm, ott, fmaf(ld, ot, conn - ppw[e]));
        }
        const size_t gi = (size_t)(base + pm) * NBUS + pb + g4 * 4;
        *(float4*)(out_d  + gi) = vo;
        *(float4*)(out_dt + gi) = vt;
        *(float4*)(out_ph + gi) = vp4;
    }
}

extern "C" void kernel_launch(void* const* d_in, const int* in_sizes, int n_in,
                              void* d_out, int out_size) {
    const float* t_in  = (const float*)d_in[0];
    const float* power = (const float*)d_in[1];
    const float* W0    = (const float*)d_in[2];
    const float* b0    = (const float*)d_in[3];
    const float* W1    = (const float*)d_in[4];
    const float* b1    = (const float*)d_in[5];
    const float* W2    = (const float*)d_in[6];
    const float* b2    = (const float*)d_in[7];
    const float* lam_m = (const float*)d_in[8];
    const float* lam_d = (const float*)d_in[9];
    const float* lam_b = (const float*)d_in[10];
    const float* bwi   = (const float*)d_in[11];

    float* out  = (float*)d_out;
    float* outt = out  + (size_t)NS * NBUS;
    float* outp = outt + (size_t)NS * NBUS;

    prep_kernel<<<32, 256>>>(W1, W2);

    cudaFuncSetAttribute(pinn_hmma_kernel, cudaFuncAttributeMaxDynamicSharedMemorySize, SMEM_TOTAL);
    pinn_hmma_kernel<<<NCTA, THREADS, SMEM_TOTAL>>>(t_in, power, W0, b0, b1, b2,
                                                    lam_m, lam_d, lam_b, bwi,
                                                    out, outt, outp);
}

// round 15
// speedup vs baseline: 4.5204x; 1.0448x over previous
#include <cuda_runtime.h>
#include <cuda_fp16.h>
#include <math.h>
#include <stdint.h>

#define NS      65536
#define NBUS    32
#define HD      256
#define MT      64            // samples per CTA
#define NCTA    (NS / MT)
#define THREADS 256
#define NGRP    4             // n-groups of 64 over HD=256

// ---- smem map (dynamic, 98304 B = A tiles only -> 2 CTAs/SM) ----
#define A_T(s)  ((s)*32768)   // 3 streams (h,p,q), each [64 m][256 k] fp16
#define SMEM_TOTAL 98304
// final-phase aliases (A region is dead by then)
#define O_OFF   0             // out      [64][32] f32
#define OT_OFF  8192          // out_t    [64][32] f32
#define OTT_OFF 16384         // out_tt   [64][32] f32
#define SCS_OFF 24576         // sin      [64][33] f32
#define SCC_OFF 33024         // cos      [64][33] f32

// ---- precomputed weight images (device globals; written by prep kernel) ----
// W1 fp16 pre-packed in mma B-fragment order:
// index = ((c*16 + kt)*2 + warpN)*64 + quad*32 + lane, one uint4 each.
// uint4 = {t.b0, t.b1, (t+1).b0, (t+1).b1} for n-tiles t = 2*quad, 2*quad+1.
__device__ __align__(16) uint4 g_w1f[8192];
// W2 fp16, pre-packed as MMA B-fragment words: [j/2 128][bus 32] half2
__device__ uint32_t g_w2p[128 * NBUS];

static __device__ __forceinline__ uint32_t s2u(const void* p) {
    uint32_t a;
    asm("{ .reg .u64 t; cvta.to.shared.u64 t, %1; cvt.u32.u64 %0, t; }" : "=r"(a) : "l"(p));
    return a;
}
static __device__ __forceinline__ uint32_t pkh(float a, float b) {
    __half2 t = __floats2half2_rn(a, b);
    return *reinterpret_cast<uint32_t*>(&t);
}
static __device__ __forceinline__ float tanh_fast(float x) {
    return 1.0f - __fdividef(2.0f, __expf(2.0f * x) + 1.0f);
}
static __device__ __forceinline__ void ldsm4(uint32_t* r, uint32_t a) {
    asm volatile("ldmatrix.sync.aligned.m8n8.x4.shared.b16 {%0,%1,%2,%3}, [%4];"
                 : "=r"(r[0]), "=r"(r[1]), "=r"(r[2]), "=r"(r[3]) : "r"(a));
}
static __device__ __forceinline__ void mma16816(float* d, const uint32_t* a,
                                                uint32_t b0, uint32_t b1) {
    asm volatile(
        "mma.sync.aligned.m16n8k16.row.col.f32.f16.f16.f32 "
        "{%0,%1,%2,%3}, {%4,%5,%6,%7}, {%8,%9}, {%0,%1,%2,%3};"
        : "+f"(d[0]), "+f"(d[1]), "+f"(d[2]), "+f"(d[3])
        : "r"(a[0]), "r"(a[1]), "r"(a[2]), "r"(a[3]), "r"(b0), "r"(b1));
}

// ============ prep kernel: pack W1 / W2 into fp16 fragment images ============
__global__ void prep_kernel(const float* __restrict__ W1, const float* __restrict__ W2) {
    const int idx = blockIdx.x * blockDim.x + threadIdx.x;   // 8192 threads
    if (idx < 8192) {
        const int lane = idx & 31;
        const int quad = (idx >> 5) & 1;
        const int wN   = (idx >> 6) & 1;
        const int kt   = (idx >> 7) & 15;
        const int c    = idx >> 11;
        const int tig  = lane & 3, gid = lane >> 2;
        const int kb   = kt * 16;
        uint32_t r[4];
        #pragma unroll
        for (int tt = 0; tt < 2; tt++) {
            const int t = quad * 2 + tt;
            const int n = c * 64 + wN * 32 + t * 8 + gid;
            r[tt * 2 + 0] = pkh(W1[(size_t)(kb + 2 * tig)     * HD + n],
                                W1[(size_t)(kb + 2 * tig + 1) * HD + n]);
            r[tt * 2 + 1] = pkh(W1[(size_t)(kb + 8 + 2 * tig) * HD + n],
                                W1[(size_t)(kb + 9 + 2 * tig) * HD + n]);
        }
        g_w1f[idx] = make_uint4(r[0], r[1], r[2], r[3]);
    }
    if (idx < 128 * NBUS) {
        const int p = idx >> 5, bus = idx & 31;       // j pair (2p, 2p+1)
        g_w2p[idx] = pkh(W2[(size_t)(2 * p) * NBUS + bus],
                         W2[(size_t)(2 * p + 1) * NBUS + bus]);
    }
}

__global__ void __launch_bounds__(THREADS, 2) pinn_hmma_kernel(
    const float* __restrict__ t_in, const float* __restrict__ power,
    const float* __restrict__ W0, const float* __restrict__ b0,
    const float* __restrict__ b1, const float* __restrict__ b2,
    const float* __restrict__ lam_m, const float* __restrict__ lam_d,
    const float* __restrict__ lam_b, const float* __restrict__ bwi,
    float* __restrict__ out_d, float* __restrict__ out_dt, float* __restrict__ out_ph)
{
    extern __shared__ __align__(1024) char smc[];
    const uint32_t sb = s2u(smc);

    const int tid   = threadIdx.x;
    const int lane  = tid & 31;
    const int wid   = tid >> 5;
    const int warpM = wid & 3;     // m-tile: rows warpM*16 .. +15
    const int warpN = wid >> 2;    // n-half within 64-group: cols warpN*32 .. +31
    const int base  = blockIdx.x * MT;

    // ============ Phase A: generate h/p/q fp16 tiles (once per CTA) ============
    // element (m,k): byte off = m*512 + (((k>>3)^(m&7))<<4) + (k&7)*2
    {
        const int gm  = tid >> 2;            // 0..63
        const int gk0 = (tid & 3) * 64;      // k range start
        const float t = __ldg(&t_in[base + gm]);
        const float x = fmaf(t, 0.1f, -1.0f);
        #pragma unroll 4
        for (int kk = 0; kk < 64; kk += 2) {
            const int k = gk0 + kk;
            float hv[2], pv[2], qv[2];
            #pragma unroll
            for (int e = 0; e < 2; e++) {
                const float w = __ldg(&W0[k + e]);
                const float d = 0.1f * w;
                const float z = fmaf(x, w, __ldg(&b0[k + e]));
                const float h = tanh_fast(z);
                const float u = 1.0f - h * h;
                hv[e] = h; pv[e] = u * d; qv[e] = -2.0f * h * u * d * d;
            }
            const uint32_t off = (uint32_t)(gm * 512 + ((((k >> 3) ^ (gm & 7))) << 4) + (k & 7) * 2);
            *(uint32_t*)(smc + A_T(0) + off) = pkh(hv[0], hv[1]);
            *(uint32_t*)(smc + A_T(1) + off) = pkh(pv[0], pv[1]);
            *(uint32_t*)(smc + A_T(2) + off) = pkh(qv[0], qv[1]);
        }
    }
    __syncthreads();

    // per-thread ldmatrix address components (x4: lanes 0-15 rows, 16-31 k-half)
    const int l16 = lane & 15;
    const int csel = lane >> 4;
    const uint32_t xr   = (uint32_t)(l16 & 7);
    const uint32_t rowA = (uint32_t)((warpM * 16 + l16) * 512);
    const int q  = lane & 3;       // C/A-frag col-pair & B-frag k-pair
    const int br = lane >> 2;      // C/A-frag row & B-frag n

    // layer-2 accumulators: out/out_t/out_tt [16m x 32bus] per warp (partial over k2)
    float acc2[3][4][4];
    #pragma unroll
    for (int s = 0; s < 3; s++)
        #pragma unroll
        for (int nb = 0; nb < 4; nb++)
            #pragma unroll
            for (int e = 0; e < 4; e++) acc2[s][nb][e] = 0.0f;

    // ============ main loop over 4 n-groups of 64 columns (no barriers) ============
    for (int c = 0; c < NGRP; c++) {
        // ---- layer-1: z/zp/zq [16m x 32n] per warp, K = 256 ----
        float acc[3][4][4];
        #pragma unroll
        for (int s = 0; s < 3; s++)
            #pragma unroll
            for (int t = 0; t < 4; t++)
                #pragma unroll
                for (int e = 0; e < 4; e++) acc[s][t][e] = 0.0f;

        const uint4* bp0 = g_w1f + ((size_t)(c * 16) * 2 + warpN) * 64 + lane;
        #pragma unroll 4
        for (int kt = 0; kt < 16; kt++) {
            const uint4 b01 = __ldg(bp0 + (size_t)kt * 128);
            const uint4 b23 = __ldg(bp0 + (size_t)kt * 128 + 32);
            const uint32_t co = (uint32_t)((((kt * 2 + csel)) ^ xr) << 4);
            uint32_t ah[3][4];
            #pragma unroll
            for (int s = 0; s < 3; s++)
                ldsm4(ah[s], sb + A_T(s) + rowA + co);
            #pragma unroll
            for (int s = 0; s < 3; s++) {
                mma16816(acc[s][0], ah[s], b01.x, b01.y);
                mma16816(acc[s][1], ah[s], b01.z, b01.w);
                mma16816(acc[s][2], ah[s], b23.x, b23.y);
                mma16816(acc[s][3], ah[s], b23.z, b23.w);
            }
        }

        // ---- in-register epilogue + layer-2, two 16-col k2 tiles ----
        const int jgw = c * 64 + warpN * 32;   // this warp's 32 j-columns
        #pragma unroll
        for (int pair = 0; pair < 2; pair++) {
            float vg[2][4], vp[2][4], vq[2][4];
            #pragma unroll
            for (int tt = 0; tt < 2; tt++) {
                const int t = pair * 2 + tt;
                const float b1a = __ldg(&b1[jgw + t * 8 + 2 * q]);
                const float b1b = __ldg(&b1[jgw + t * 8 + 2 * q + 1]);
                #pragma unroll
                for (int e = 0; e < 4; e++) {
                    const float zh = acc[0][t][e] + ((e & 1) ? b1b : b1a);
                    const float zp = acc[1][t][e];
                    const float zq = acc[2][t][e];
                    const float g  = tanh_fast(zh);
                    const float u  = 1.0f - g * g;
                    vg[tt][e] = g;
                    vp[tt][e] = u * zp;
                    vq[tt][e] = u * fmaf(-2.0f * g * zp, zp, zq);
                }
            }
            // W2 frags (precomputed fp16 fragment words)
            const int jp = jgw + pair * 16;
            const int p0 = (jp + 2 * q) >> 1;
            const int p1 = (jp + 8 + 2 * q) >> 1;
            uint32_t w2f[4][2];
            #pragma unroll
            for (int nb = 0; nb < 4; nb++) {
                const int bus = nb * 8 + br;
                w2f[nb][0] = __ldg(&g_w2p[p0 * NBUS + bus]);
                w2f[nb][1] = __ldg(&g_w2p[p1 * NBUS + bus]);
            }
            #pragma unroll
            for (int s = 0; s < 3; s++) {
                const float (*v)[4] = (s == 0) ? vg : (s == 1) ? vp : vq;
                uint32_t a2[4];
                a2[0] = pkh(v[0][0], v[0][1]);
                a2[1] = pkh(v[0][2], v[0][3]);
                a2[2] = pkh(v[1][0], v[1][1]);
                a2[3] = pkh(v[1][2], v[1][3]);
                #pragma unroll
                for (int nb = 0; nb < 4; nb++)
                    mma16816(acc2[s][nb], a2, w2f[nb][0], w2f[nb][1]);
            }
        }
    }

    // ============ cross-warp k2 reduction + physics ============
    __syncthreads();   // all A smem reads done -> safe to alias
    float* f_o   = (float*)(smc + O_OFF);
    float* f_ot  = (float*)(smc + OT_OFF);
    float* f_ott = (float*)(smc + OTT_OFF);
    float* scs   = (float*)(smc + SCS_OFF);
    float* scc   = (float*)(smc + SCC_OFF);

    if (warpN == 0) {
        #pragma unroll
        for (int s = 0; s < 3; s++) {
            float* dst = (s == 0) ? f_o : (s == 1) ? f_ot : f_ott;
            #pragma unroll
            for (int nb = 0; nb < 4; nb++)
                #pragma unroll
                for (int e = 0; e < 4; e++) {
                    const int row = warpM * 16 + br + ((e >> 1) << 3);
                    const int bus = nb * 8 + 2 * q + (e & 1);
                    dst[row * NBUS + bus] = acc2[s][nb][e];
                }
        }
    }
    __syncthreads();
    if (warpN == 1) {
        #pragma unroll
        for (int s = 0; s < 3; s++) {
            float* dst = (s == 0) ? f_o : (s == 1) ? f_ot : f_ott;
            #pragma unroll
            for (int nb = 0; nb < 4; nb++)
                #pragma unroll
                for (int e = 0; e < 4; e++) {
                    const int row = warpM * 16 + br + ((e >> 1) << 3);
                    const int bus = nb * 8 + 2 * q + (e & 1);
                    float v = dst[row * NBUS + bus] + acc2[s][nb][e];
                    if (s == 0) v += __ldg(&b2[bus]);
                    dst[row * NBUS + bus] = v;
                }
        }
    }
    __syncthreads();

    // sin/cos tables
    #pragma unroll
    for (int i = 0; i < 8; i++) {
        const int cell = tid * 8 + i;
        const int m = cell >> 5, bus = cell & 31;
        float sv, cv;
        __sincosf(f_o[cell], &sv, &cv);
        scs[m * 33 + bus] = sv;
        scc[m * 33 + bus] = cv;
    }
    __syncthreads();

    // physics: thread -> sample pm, buses pb..pb+7
    const int pm = tid >> 2;
    const int pb = (tid & 3) * 8;
    #pragma unroll
    for (int g4 = 0; g4 < 2; g4++) {
        float4 vo, vt, vp4;
        float* po = &vo.x; float* pt = &vt.x; float* pp = &vp4.x;
        const float4 pw = __ldg((const float4*)(power + (size_t)(base + pm) * NBUS + pb + g4 * 4));
        const float* ppw = &pw.x;
        #pragma unroll
        for (int e = 0; e < 4; e++) {
            const int bus = pb + g4 * 4 + e;
            const float o   = f_o  [pm * NBUS + bus];
            const float ot  = f_ot [pm * NBUS + bus];
            const float ott = f_ott[pm * NBUS + bus];
            float accC = 0.0f, accS = 0.0f;
            #pragma unroll
            for (int j = 0; j < NBUS; j++) {
                const float bl2 = __ldg(&lam_b[bus * NBUS + j]);
                accC = fmaf(bl2, scc[pm * 33 + j], accC);
                accS = fmaf(bl2, scs[pm * 33 + j], accS);
            }
            const float conn = scs[pm * 33 + bus] * accC - scc[pm * 33 + bus] * accS;
            const float lm = __ldg(&lam_m[bus]) * __ldg(&bwi[bus]);
            const float ld = __ldg(&lam_d[bus]);
            po[e] = o;
            pt[e] = ot;
            pp[e] = fmaf(lm, ott, fmaf(ld, ot, conn - ppw[e]));
        }
        const size_t gi = (size_t)(base + pm) * NBUS + pb + g4 * 4;
        *(float4*)(out_d  + gi) = vo;
        *(float4*)(out_dt + gi) = vt;
        *(float4*)(out_ph + gi) = vp4;
    }
}

extern "C" void kernel_launch(void* const* d_in, const int* in_sizes, int n_in,
                              void* d_out, int out_size) {
    const float* t_in  = (const float*)d_in[0];
    const float* power = (const float*)d_in[1];
    const float* W0    = (const float*)d_in[2];
    const float* b0    = (const float*)d_in[3];
    const float* W1    = (const float*)d_in[4];
    const float* b1    = (const float*)d_in[5];
    const float* W2    = (const float*)d_in[6];
    const float* b2    = (const float*)d_in[7];
    const float* lam_m = (const float*)d_in[8];
    const float* lam_d = (const float*)d_in[9];
    const float* lam_b = (const float*)d_in[10];
    const float* bwi   = (const float*)d_in[11];

    float* out  = (float*)d_out;
    float* outt = out  + (size_t)NS * NBUS;
    float* outp = outt + (size_t)NS * NBUS;

    prep_kernel<<<32, 256>>>(W1, W2);

    cudaFuncSetAttribute(pinn_hmma_kernel, cudaFuncAttributeMaxDynamicSharedMemorySize, SMEM_TOTAL);
    pinn_hmma_kernel<<<NCTA, THREADS, SMEM_TOTAL>>>(t_in, power, W0, b0, b1, b2,
                                                    lam_m, lam_d, lam_b, bwi,
                                                    out, outt, outp);
}

// round 16
// speedup vs baseline: 4.7738x; 1.0561x over previous
#include <cuda_runtime.h>
#include <cuda_fp16.h>
#include <math.h>
#include <stdint.h>

#define NS      65536
#define NBUS    32
#define HD      256
#define MT      64            // samples per CTA (kernel 1)
#define NCTA    (NS / MT)
#define THREADS 256
#define NGRP    4             // n-groups of 64 over HD=256
#define MT2     128           // samples per CTA (kernel 2)
#define NCTA2   (NS / MT2)

// ---- kernel1 smem: A tiles only (3 x [64 m][256 k] fp16 = 98304 B) ----
#define A_T(s)  ((s)*32768)
#define SMEM_TOTAL 98304

// ---- kernel2 smem ----
#define K2_O    0             // out    [128][32] f32
#define K2_OT   16384         // out_t
#define K2_OTT  32768         // out_tt
#define K2_SCS  49152         // sin    [128][33] f32
#define K2_SCC  66048         // cos    [128][33] f32
#define K2_SMEM 82944

// ---- precomputed weight images (device globals; written by prep kernel) ----
// W1 fp16 pre-packed in mma B-fragment order (see R10 notes).
__device__ __align__(16) uint4 g_w1f[8192];
// W2 fp16, pre-packed as MMA B-fragment words: [j/2 128][bus 32] half2
__device__ uint32_t g_w2p[128 * NBUS];
// Inter-kernel staging: layer-2 A-fragments of G/G'/G'' in fragment order.
// index = ((s*4096 + mt)*16 + kt2)*32 + lane   (mt = global 16-row m-tile)
__device__ __align__(16) uint4 g_G[3u * 4096 * 16 * 32];

static __device__ __forceinline__ uint32_t s2u(const void* p) {
    uint32_t a;
    asm("{ .reg .u64 t; cvta.to.shared.u64 t, %1; cvt.u32.u64 %0, t; }" : "=r"(a) : "l"(p));
    return a;
}
static __device__ __forceinline__ uint32_t pkh(float a, float b) {
    __half2 t = __floats2half2_rn(a, b);
    return *reinterpret_cast<uint32_t*>(&t);
}
static __device__ __forceinline__ float tanh_fast(float x) {
    return 1.0f - __fdividef(2.0f, __expf(2.0f * x) + 1.0f);
}
static __device__ __forceinline__ void ldsm4(uint32_t* r, uint32_t a) {
    asm volatile("ldmatrix.sync.aligned.m8n8.x4.shared.b16 {%0,%1,%2,%3}, [%4];"
                 : "=r"(r[0]), "=r"(r[1]), "=r"(r[2]), "=r"(r[3]) : "r"(a));
}
static __device__ __forceinline__ void mma16816(float* d, const uint32_t* a,
                                                uint32_t b0, uint32_t b1) {
    asm volatile(
        "mma.sync.aligned.m16n8k16.row.col.f32.f16.f16.f32 "
        "{%0,%1,%2,%3}, {%4,%5,%6,%7}, {%8,%9}, {%0,%1,%2,%3};"
        : "+f"(d[0]), "+f"(d[1]), "+f"(d[2]), "+f"(d[3])
        : "r"(a[0]), "r"(a[1]), "r"(a[2]), "r"(a[3]), "r"(b0), "r"(b1));
}

// ============ prep kernel: pack W1 / W2 into fp16 fragment images ============
__global__ void prep_kernel(const float* __restrict__ W1, const float* __restrict__ W2) {
    const int idx = blockIdx.x * blockDim.x + threadIdx.x;   // 8192 threads
    if (idx < 8192) {
        const int lane = idx & 31;
        const int quad = (idx >> 5) & 1;
        const int wN   = (idx >> 6) & 1;
        const int kt   = (idx >> 7) & 15;
        const int c    = idx >> 11;
        const int tig  = lane & 3, gid = lane >> 2;
        const int kb   = kt * 16;
        uint32_t r[4];
        #pragma unroll
        for (int tt = 0; tt < 2; tt++) {
            const int t = quad * 2 + tt;
            const int n = c * 64 + wN * 32 + t * 8 + gid;
            r[tt * 2 + 0] = pkh(W1[(size_t)(kb + 2 * tig)     * HD + n],
                                W1[(size_t)(kb + 2 * tig + 1) * HD + n]);
            r[tt * 2 + 1] = pkh(W1[(size_t)(kb + 8 + 2 * tig) * HD + n],
                                W1[(size_t)(kb + 9 + 2 * tig) * HD + n]);
        }
        g_w1f[idx] = make_uint4(r[0], r[1], r[2], r[3]);
    }
    if (idx < 128 * NBUS) {
        const int p = idx >> 5, bus = idx & 31;       // j pair (2p, 2p+1)
        g_w2p[idx] = pkh(W2[(size_t)(2 * p) * NBUS + bus],
                         W2[(size_t)(2 * p + 1) * NBUS + bus]);
    }
}

// ============ kernel 1: layer-1 GEMM + tanh chain -> G fragments ============
__global__ void __launch_bounds__(THREADS, 2) pinn_l1_kernel(
    const float* __restrict__ t_in, const float* __restrict__ W0,
    const float* __restrict__ b0, const float* __restrict__ b1)
{
    extern __shared__ __align__(1024) char smc[];
    const uint32_t sb = s2u(smc);

    const int tid   = threadIdx.x;
    const int lane  = tid & 31;
    const int wid   = tid >> 5;
    const int warpM = wid & 3;     // m-tile: rows warpM*16 .. +15
    const int warpN = wid >> 2;    // n-half within 64-group
    const int base  = blockIdx.x * MT;
    const int mt    = blockIdx.x * 4 + warpM;   // global 16-row m-tile index

    // ---- Phase A: generate h/p/q fp16 tiles ----
    {
        const int gm  = tid >> 2;
        const int gk0 = (tid & 3) * 64;
        const float t = __ldg(&t_in[base + gm]);
        const float x = fmaf(t, 0.1f, -1.0f);
        #pragma unroll 4
        for (int kk = 0; kk < 64; kk += 2) {
            const int k = gk0 + kk;
            float hv[2], pv[2], qv[2];
            #pragma unroll
            for (int e = 0; e < 2; e++) {
                const float w = __ldg(&W0[k + e]);
                const float d = 0.1f * w;
                const float z = fmaf(x, w, __ldg(&b0[k + e]));
                const float h = tanh_fast(z);
                const float u = 1.0f - h * h;
                hv[e] = h; pv[e] = u * d; qv[e] = -2.0f * h * u * d * d;
            }
            const uint32_t off = (uint32_t)(gm * 512 + ((((k >> 3) ^ (gm & 7))) << 4) + (k & 7) * 2);
            *(uint32_t*)(smc + A_T(0) + off) = pkh(hv[0], hv[1]);
            *(uint32_t*)(smc + A_T(1) + off) = pkh(pv[0], pv[1]);
            *(uint32_t*)(smc + A_T(2) + off) = pkh(qv[0], qv[1]);
        }
    }
    __syncthreads();

    const int l16 = lane & 15;
    const int csel = lane >> 4;
    const uint32_t xr   = (uint32_t)(l16 & 7);
    const uint32_t rowA = (uint32_t)((warpM * 16 + l16) * 512);
    const int q  = lane & 3;

    // ---- main loop over 4 n-groups of 64 columns (no barriers) ----
    for (int c = 0; c < NGRP; c++) {
        float acc[3][4][4];
        #pragma unroll
        for (int s = 0; s < 3; s++)
            #pragma unroll
            for (int t = 0; t < 4; t++)
                #pragma unroll
                for (int e = 0; e < 4; e++) acc[s][t][e] = 0.0f;

        const uint4* bp0 = g_w1f + ((size_t)(c * 16) * 2 + warpN) * 64 + lane;
        #pragma unroll 4
        for (int kt = 0; kt < 16; kt++) {
            const uint4 b01 = __ldg(bp0 + (size_t)kt * 128);
            const uint4 b23 = __ldg(bp0 + (size_t)kt * 128 + 32);
            const uint32_t co = (uint32_t)((((kt * 2 + csel)) ^ xr) << 4);
            uint32_t ah[3][4];
            #pragma unroll
            for (int s = 0; s < 3; s++)
                ldsm4(ah[s], sb + A_T(s) + rowA + co);
            #pragma unroll
            for (int s = 0; s < 3; s++) {
                mma16816(acc[s][0], ah[s], b01.x, b01.y);
                mma16816(acc[s][1], ah[s], b01.z, b01.w);
                mma16816(acc[s][2], ah[s], b23.x, b23.y);
                mma16816(acc[s][3], ah[s], b23.z, b23.w);
            }
        }

        // ---- epilogue: bias + tanh chain -> packed layer-2 A-frags -> global ----
        const int jgw = c * 64 + warpN * 32;
        #pragma unroll
        for (int pair = 0; pair < 2; pair++) {
            float vg[2][4], vp[2][4], vq[2][4];
            #pragma unroll
            for (int tt = 0; tt < 2; tt++) {
                const int t = pair * 2 + tt;
                const float b1a = __ldg(&b1[jgw + t * 8 + 2 * q]);
                const float b1b = __ldg(&b1[jgw + t * 8 + 2 * q + 1]);
                #pragma unroll
                for (int e = 0; e < 4; e++) {
                    const float zh = acc[0][t][e] + ((e & 1) ? b1b : b1a);
                    const float zp = acc[1][t][e];
                    const float zq = acc[2][t][e];
                    const float g  = tanh_fast(zh);
                    const float u  = 1.0f - g * g;
                    vg[tt][e] = g;
                    vp[tt][e] = u * zp;
                    vq[tt][e] = u * fmaf(-2.0f * g * zp, zp, zq);
                }
            }
            const int kt2 = c * 4 + warpN * 2 + pair;   // global k2 tile 0..15
            #pragma unroll
            for (int s = 0; s < 3; s++) {
                const float (*v)[4] = (s == 0) ? vg : (s == 1) ? vp : vq;
                uint4 a2;
                a2.x = pkh(v[0][0], v[0][1]);
                a2.y = pkh(v[0][2], v[0][3]);
                a2.z = pkh(v[1][0], v[1][1]);
                a2.w = pkh(v[1][2], v[1][3]);
                g_G[(((size_t)s * 4096 + mt) * 16 + kt2) * 32 + lane] = a2;
            }
        }
    }
}

// ============ kernel 2: layer-2 GEMM + physics ============
__global__ void __launch_bounds__(THREADS, 2) pinn_l2_kernel(
    const float* __restrict__ power, const float* __restrict__ b2,
    const float* __restrict__ lam_m, const float* __restrict__ lam_d,
    const float* __restrict__ lam_b, const float* __restrict__ bwi,
    float* __restrict__ out_d, float* __restrict__ out_dt, float* __restrict__ out_ph)
{
    extern __shared__ __align__(1024) char smc[];
    const int tid  = threadIdx.x;
    const int lane = tid & 31;
    const int wid  = tid >> 5;
    const int base = blockIdx.x * MT2;
    const int mt   = blockIdx.x * 8 + wid;      // this warp's global m-tile
    const int q  = lane & 3;
    const int br = lane >> 2;

    float acc2[3][4][4];
    #pragma unroll
    for (int s = 0; s < 3; s++)
        #pragma unroll
        for (int nb = 0; nb < 4; nb++)
            #pragma unroll
            for (int e = 0; e < 4; e++) acc2[s][nb][e] = 0.0f;

    #pragma unroll 4
    for (int kt2 = 0; kt2 < 16; kt2++) {
        uint4 a2v[3];
        #pragma unroll
        for (int s = 0; s < 3; s++)
            a2v[s] = __ldg(&g_G[(((size_t)s * 4096 + mt) * 16 + kt2) * 32 + lane]);
        const int p0 = (kt2 * 16 + 2 * q) >> 1;
        uint32_t w2f[4][2];
        #pragma unroll
        for (int nb = 0; nb < 4; nb++) {
            const int bus = nb * 8 + br;
            w2f[nb][0] = __ldg(&g_w2p[p0 * NBUS + bus]);
            w2f[nb][1] = __ldg(&g_w2p[(p0 + 4) * NBUS + bus]);
        }
        #pragma unroll
        for (int s = 0; s < 3; s++) {
            const uint32_t a2[4] = {a2v[s].x, a2v[s].y, a2v[s].z, a2v[s].w};
            #pragma unroll
            for (int nb = 0; nb < 4; nb++)
                mma16816(acc2[s][nb], a2, w2f[nb][0], w2f[nb][1]);
        }
    }

    // ---- write frags to smem (each warp owns its 16 rows fully) ----
    float* f_o   = (float*)(smc + K2_O);
    float* f_ot  = (float*)(smc + K2_OT);
    float* f_ott = (float*)(smc + K2_OTT);
    float* scs   = (float*)(smc + K2_SCS);
    float* scc   = (float*)(smc + K2_SCC);

    #pragma unroll
    for (int s = 0; s < 3; s++) {
        float* dst = (s == 0) ? f_o : (s == 1) ? f_ot : f_ott;
        #pragma unroll
        for (int nb = 0; nb < 4; nb++)
            #pragma unroll
            for (int e = 0; e < 4; e++) {
                const int row = wid * 16 + br + ((e >> 1) << 3);
                const int bus = nb * 8 + 2 * q + (e & 1);
                float v = acc2[s][nb][e];
                if (s == 0) v += __ldg(&b2[bus]);
                dst[row * NBUS + bus] = v;
            }
    }
    __syncthreads();

    // sin/cos tables: 128*32 = 4096 cells, 16 per thread
    #pragma unroll
    for (int i = 0; i < 16; i++) {
        const int cell = tid * 16 + i;
        const int m = cell >> 5, bus = cell & 31;
        float sv, cv;
        __sincosf(f_o[cell], &sv, &cv);
        scs[m * 33 + bus] = sv;
        scc[m * 33 + bus] = cv;
    }
    __syncthreads();

    // physics: thread -> sample pm, 16 buses
    const int pm = tid >> 1;
    const int pb = (tid & 1) * 16;
    #pragma unroll
    for (int g4 = 0; g4 < 4; g4++) {
        float4 vo, vt, vp4;
        float* po = &vo.x; float* pt = &vt.x; float* pp = &vp4.x;
        const float4 pw = __ldg((const float4*)(power + (size_t)(base + pm) * NBUS + pb + g4 * 4));
        const float* ppw = &pw.x;
        #pragma unroll
        for (int e = 0; e < 4; e++) {
            const int bus = pb + g4 * 4 + e;
            const float o   = f_o  [pm * NBUS + bus];
            const float ot  = f_ot [pm * NBUS + bus];
            const float ott = f_ott[pm * NBUS + bus];
            float accC = 0.0f, accS = 0.0f;
            #pragma unroll
            for (int j = 0; j < NBUS; j++) {
                const float bl2 = __ldg(&lam_b[bus * NBUS + j]);
                accC = fmaf(bl2, scc[pm * 33 + j], accC);
                accS = fmaf(bl2, scs[pm * 33 + j], accS);
            }
            const float conn = scs[pm * 33 + bus] * accC - scc[pm * 33 + bus] * accS;
            const float lm = __ldg(&lam_m[bus]) * __ldg(&bwi[bus]);
            const float ld = __ldg(&lam_d[bus]);
            po[e] = o;
            pt[e] = ot;
            pp[e] = fmaf(lm, ott, fmaf(ld, ot, conn - ppw[e]));
        }
        const size_t gi = (size_t)(base + pm) * NBUS + pb + g4 * 4;
        *(float4*)(out_d  + gi) = vo;
        *(float4*)(out_dt + gi) = vt;
        *(float4*)(out_ph + gi) = vp4;
    }
}

extern "C" void kernel_launch(void* const* d_in, const int* in_sizes, int n_in,
                              void* d_out, int out_size) {
    const float* t_in  = (const float*)d_in[0];
    const float* power = (const float*)d_in[1];
    const float* W0    = (const float*)d_in[2];
    const float* b0    = (const float*)d_in[3];
    const float* W1    = (const float*)d_in[4];
    const float* b1    = (const float*)d_in[5];
    const float* W2    = (const float*)d_in[6];
    const float* b2    = (const float*)d_in[7];
    const float* lam_m = (const float*)d_in[8];
    const float* lam_d = (const float*)d_in[9];
    const float* lam_b = (const float*)d_in[10];
    const float* bwi   = (const float*)d_in[11];

    float* out  = (float*)d_out;
    float* outt = out  + (size_t)NS * NBUS;
    float* outp = outt + (size_t)NS * NBUS;

    prep_kernel<<<32, 256>>>(W1, W2);

    cudaFuncSetAttribute(pinn_l1_kernel, cudaFuncAttributeMaxDynamicSharedMemorySize, SMEM_TOTAL);
    pinn_l1_kernel<<<NCTA, THREADS, SMEM_TOTAL>>>(t_in, W0, b0, b1);

    cudaFuncSetAttribute(pinn_l2_kernel, cudaFuncAttributeMaxDynamicSharedMemorySize, K2_SMEM);
    pinn_l2_kernel<<<NCTA2, THREADS, K2_SMEM>>>(power, b2, lam_m, lam_d, lam_b, bwi,
                                                out, outt, outp);
}

// round 17
// speedup vs baseline: 4.9624x; 1.0395x over previous
#include <cuda_runtime.h>
#include <cuda_fp16.h>
#include <math.h>
#include <stdint.h>

#define NS      65536
#define NBUS    32
#define HD      256
#define MT      64            // samples per CTA (kernel 1)
#define NCTA    (NS / MT)
#define THREADS 256
#define NGRP    4             // n-groups of 64 over HD=256
#define MT2     128           // samples per CTA (kernel 2)
#define NCTA2   (NS / MT2)

// ---- kernel1 smem: A tiles only (3 x [64 m][256 k] fp16 = 98304 B) ----
#define A_T(s)  ((s)*32768)
#define SMEM_TOTAL 98304

// ---- kernel2 smem ----
#define K2_O    0             // out    [128][32] f32
#define K2_OT   16384         // out_t
#define K2_OTT  32768         // out_tt
#define K2_SCS  49152         // sin    [128][33] f32
#define K2_SCC  66048         // cos    [128][33] f32
#define K2_SMEM 82944

// ---- precomputed weight images (device globals; written by prep kernel) ----
__device__ __align__(16) uint4 g_w1f[8192];
__device__ uint32_t g_w2p[128 * NBUS];
// Inter-kernel staging: layer-2 A-fragments of G/G'/G'' in fragment order.
// index = ((s*4096 + mt)*16 + kt2)*32 + lane   (mt = global 16-row m-tile)
__device__ __align__(16) uint4 g_G[3u * 4096 * 16 * 32];

static __device__ __forceinline__ uint32_t s2u(const void* p) {
    uint32_t a;
    asm("{ .reg .u64 t; cvta.to.shared.u64 t, %1; cvt.u32.u64 %0, t; }" : "=r"(a) : "l"(p));
    return a;
}
static __device__ __forceinline__ uint32_t pkh(float a, float b) {
    __half2 t = __floats2half2_rn(a, b);
    return *reinterpret_cast<uint32_t*>(&t);
}
static __device__ __forceinline__ float tanh_fast(float x) {
    return 1.0f - __fdividef(2.0f, __expf(2.0f * x) + 1.0f);
}
static __device__ __forceinline__ void ldsm4(uint32_t* r, uint32_t a) {
    asm volatile("ldmatrix.sync.aligned.m8n8.x4.shared.b16 {%0,%1,%2,%3}, [%4];"
                 : "=r"(r[0]), "=r"(r[1]), "=r"(r[2]), "=r"(r[3]) : "r"(a));
}
static __device__ __forceinline__ void mma16816(float* d, const uint32_t* a,
                                                uint32_t b0, uint32_t b1) {
    asm volatile(
        "mma.sync.aligned.m16n8k16.row.col.f32.f16.f16.f32 "
        "{%0,%1,%2,%3}, {%4,%5,%6,%7}, {%8,%9}, {%0,%1,%2,%3};"
        : "+f"(d[0]), "+f"(d[1]), "+f"(d[2]), "+f"(d[3])
        : "r"(a[0]), "r"(a[1]), "r"(a[2]), "r"(a[3]), "r"(b0), "r"(b1));
}

// ============ prep kernel: pack W1 / W2 into fp16 fragment images ============
__global__ void prep_kernel(const float* __restrict__ W1, const float* __restrict__ W2) {
    const int idx = blockIdx.x * blockDim.x + threadIdx.x;   // 8192 threads
    if (idx < 8192) {
        const int lane = idx & 31;
        const int quad = (idx >> 5) & 1;
        const int wN   = (idx >> 6) & 1;
        const int kt   = (idx >> 7) & 15;
        const int c    = idx >> 11;
        const int tig  = lane & 3, gid = lane >> 2;
        const int kb   = kt * 16;
        uint32_t r[4];
        #pragma unroll
        for (int tt = 0; tt < 2; tt++) {
            const int t = quad * 2 + tt;
            const int n = c * 64 + wN * 32 + t * 8 + gid;
            r[tt * 2 + 0] = pkh(W1[(size_t)(kb + 2 * tig)     * HD + n],
                                W1[(size_t)(kb + 2 * tig + 1) * HD + n]);
            r[tt * 2 + 1] = pkh(W1[(size_t)(kb + 8 + 2 * tig) * HD + n],
                                W1[(size_t)(kb + 9 + 2 * tig) * HD + n]);
        }
        g_w1f[idx] = make_uint4(r[0], r[1], r[2], r[3]);
    }
    if (idx < 128 * NBUS) {
        const int p = idx >> 5, bus = idx & 31;       // j pair (2p, 2p+1)
        g_w2p[idx] = pkh(W2[(size_t)(2 * p) * NBUS + bus],
                         W2[(size_t)(2 * p + 1) * NBUS + bus]);
    }
}

// ============ kernel 1: layer-1 GEMM + tanh chain -> G fragments ============
__global__ void __launch_bounds__(THREADS, 2) pinn_l1_kernel(
    const float* __restrict__ t_in, const float* __restrict__ W0,
    const float* __restrict__ b0, const float* __restrict__ b1)
{
    extern __shared__ __align__(1024) char smc[];
    const uint32_t sb = s2u(smc);

    const int tid   = threadIdx.x;
    const int lane  = tid & 31;
    const int wid   = tid >> 5;
    const int warpM = wid & 3;     // m-tile: rows warpM*16 .. +15
    const int warpN = wid >> 2;    // n-half within 64-group
    const int base  = blockIdx.x * MT;
    const int mt    = blockIdx.x * 4 + warpM;   // global 16-row m-tile index

    // ---- Phase A: generate h/p/q fp16 tiles ----
    {
        const int gm  = tid >> 2;
        const int gk0 = (tid & 3) * 64;
        const float t = __ldg(&t_in[base + gm]);
        const float x = fmaf(t, 0.1f, -1.0f);
        #pragma unroll 4
        for (int kk = 0; kk < 64; kk += 2) {
            const int k = gk0 + kk;
            float hv[2], pv[2], qv[2];
            #pragma unroll
            for (int e = 0; e < 2; e++) {
                const float w = __ldg(&W0[k + e]);
                const float d = 0.1f * w;
                const float z = fmaf(x, w, __ldg(&b0[k + e]));
                const float h = tanh_fast(z);
                const float u = 1.0f - h * h;
                hv[e] = h; pv[e] = u * d; qv[e] = -2.0f * h * u * d * d;
            }
            const uint32_t off = (uint32_t)(gm * 512 + ((((k >> 3) ^ (gm & 7))) << 4) + (k & 7) * 2);
            *(uint32_t*)(smc + A_T(0) + off) = pkh(hv[0], hv[1]);
            *(uint32_t*)(smc + A_T(1) + off) = pkh(pv[0], pv[1]);
            *(uint32_t*)(smc + A_T(2) + off) = pkh(qv[0], qv[1]);
        }
    }
    __syncthreads();

    const int l16 = lane & 15;
    const int csel = lane >> 4;
    const uint32_t xr   = (uint32_t)(l16 & 7);
    const uint32_t rowA = (uint32_t)((warpM * 16 + l16) * 512);
    const int q  = lane & 3;

    // ---- main loop over 4 n-groups of 64 columns (no barriers) ----
    for (int c = 0; c < NGRP; c++) {
        float acc[3][4][4];
        #pragma unroll
        for (int s = 0; s < 3; s++)
            #pragma unroll
            for (int t = 0; t < 4; t++)
                #pragma unroll
                for (int e = 0; e < 4; e++) acc[s][t][e] = 0.0f;

        const uint4* bp0 = g_w1f + ((size_t)(c * 16) * 2 + warpN) * 64 + lane;

        // software pipeline: prefetch kt=0
        uint4 b01 = __ldg(bp0);
        uint4 b23 = __ldg(bp0 + 32);
        uint32_t ah[3][4];
        {
            const uint32_t co = (uint32_t)((csel ^ xr) << 4);
            #pragma unroll
            for (int s = 0; s < 3; s++)
                ldsm4(ah[s], sb + A_T(s) + rowA + co);
        }
        #pragma unroll
        for (int kt = 0; kt < 16; kt++) {
            uint4 nb01, nb23;
            uint32_t nah[3][4];
            if (kt < 15) {
                nb01 = __ldg(bp0 + (size_t)(kt + 1) * 128);
                nb23 = __ldg(bp0 + (size_t)(kt + 1) * 128 + 32);
                const uint32_t co = (uint32_t)(((((kt + 1) * 2 + csel)) ^ xr) << 4);
                #pragma unroll
                for (int s = 0; s < 3; s++)
                    ldsm4(nah[s], sb + A_T(s) + rowA + co);
            }
            #pragma unroll
            for (int s = 0; s < 3; s++) {
                mma16816(acc[s][0], ah[s], b01.x, b01.y);
                mma16816(acc[s][1], ah[s], b01.z, b01.w);
                mma16816(acc[s][2], ah[s], b23.x, b23.y);
                mma16816(acc[s][3], ah[s], b23.z, b23.w);
            }
            if (kt < 15) {
                b01 = nb01; b23 = nb23;
                #pragma unroll
                for (int s = 0; s < 3; s++)
                    #pragma unroll
                    for (int e = 0; e < 4; e++) ah[s][e] = nah[s][e];
            }
        }

        // ---- epilogue: bias + tanh chain -> packed layer-2 A-frags -> global ----
        const int jgw = c * 64 + warpN * 32;
        #pragma unroll
        for (int pair = 0; pair < 2; pair++) {
            float vg[2][4], vp[2][4], vq[2][4];
            #pragma unroll
            for (int tt = 0; tt < 2; tt++) {
                const int t = pair * 2 + tt;
                const float b1a = __ldg(&b1[jgw + t * 8 + 2 * q]);
                const float b1b = __ldg(&b1[jgw + t * 8 + 2 * q + 1]);
                #pragma unroll
                for (int e = 0; e < 4; e++) {
                    const float zh = acc[0][t][e] + ((e & 1) ? b1b : b1a);
                    const float zp = acc[1][t][e];
                    const float zq = acc[2][t][e];
                    const float g  = tanh_fast(zh);
                    const float u  = 1.0f - g * g;
                    vg[tt][e] = g;
                    vp[tt][e] = u * zp;
                    vq[tt][e] = u * fmaf(-2.0f * g * zp, zp, zq);
                }
            }
            const int kt2 = c * 4 + warpN * 2 + pair;   // global k2 tile 0..15
            #pragma unroll
            for (int s = 0; s < 3; s++) {
                const float (*v)[4] = (s == 0) ? vg : (s == 1) ? vp : vq;
                uint4 a2;
                a2.x = pkh(v[0][0], v[0][1]);
                a2.y = pkh(v[0][2], v[0][3]);
                a2.z = pkh(v[1][0], v[1][1]);
                a2.w = pkh(v[1][2], v[1][3]);
                g_G[(((size_t)s * 4096 + mt) * 16 + kt2) * 32 + lane] = a2;
            }
        }
    }
}

// ============ kernel 2: layer-2 GEMM + physics ============
__global__ void __launch_bounds__(THREADS, 2) pinn_l2_kernel(
    const float* __restrict__ power, const float* __restrict__ b2,
    const float* __restrict__ lam_m, const float* __restrict__ lam_d,
    const float* __restrict__ lam_b, const float* __restrict__ bwi,
    float* __restrict__ out_d, float* __restrict__ out_dt, float* __restrict__ out_ph)
{
    extern __shared__ __align__(1024) char smc[];
    const int tid  = threadIdx.x;
    const int lane = tid & 31;
    const int wid  = tid >> 5;
    const int base = blockIdx.x * MT2;
    const int mt   = blockIdx.x * 8 + wid;      // this warp's global m-tile
    const int q  = lane & 3;
    const int br = lane >> 2;

    float acc2[3][4][4];
    #pragma unroll
    for (int s = 0; s < 3; s++)
        #pragma unroll
        for (int nb = 0; nb < 4; nb++)
            #pragma unroll
            for (int e = 0; e < 4; e++) acc2[s][nb][e] = 0.0f;

    // fully unrolled: ptxas front-batches the independent DRAM loads (MLP)
    #pragma unroll
    for (int kt2 = 0; kt2 < 16; kt2++) {
        uint4 a2v[3];
        #pragma unroll
        for (int s = 0; s < 3; s++)
            a2v[s] = __ldg(&g_G[(((size_t)s * 4096 + mt) * 16 + kt2) * 32 + lane]);
        const int p0 = (kt2 * 16 + 2 * q) >> 1;
        uint32_t w2f[4][2];
        #pragma unroll
        for (int nb = 0; nb < 4; nb++) {
            const int bus = nb * 8 + br;
            w2f[nb][0] = __ldg(&g_w2p[p0 * NBUS + bus]);
            w2f[nb][1] = __ldg(&g_w2p[(p0 + 4) * NBUS + bus]);
        }
        #pragma unroll
        for (int s = 0; s < 3; s++) {
            const uint32_t a2[4] = {a2v[s].x, a2v[s].y, a2v[s].z, a2v[s].w};
            #pragma unroll
            for (int nb = 0; nb < 4; nb++)
                mma16816(acc2[s][nb], a2, w2f[nb][0], w2f[nb][1]);
        }
    }

    // ---- write frags to smem (each warp owns its 16 rows fully) ----
    float* f_o   = (float*)(smc + K2_O);
    float* f_ot  = (float*)(smc + K2_OT);
    float* f_ott = (float*)(smc + K2_OTT);
    float* scs   = (float*)(smc + K2_SCS);
    float* scc   = (float*)(smc + K2_SCC);

    #pragma unroll
    for (int s = 0; s < 3; s++) {
        float* dst = (s == 0) ? f_o : (s == 1) ? f_ot : f_ott;
        #pragma unroll
        for (int nb = 0; nb < 4; nb++)
            #pragma unroll
            for (int e = 0; e < 4; e++) {
                const int row = wid * 16 + br + ((e >> 1) << 3);
                const int bus = nb * 8 + 2 * q + (e & 1);
                float v = acc2[s][nb][e];
                if (s == 0) v += __ldg(&b2[bus]);
                dst[row * NBUS + bus] = v;
            }
    }
    __syncthreads();

    // sin/cos tables: 128*32 = 4096 cells, 16 per thread
    #pragma unroll
    for (int i = 0; i < 16; i++) {
        const int cell = tid * 16 + i;
        const int m = cell >> 5, bus = cell & 31;
        float sv, cv;
        __sincosf(f_o[cell], &sv, &cv);
        scs[m * 33 + bus] = sv;
        scc[m * 33 + bus] = cv;
    }
    __syncthreads();

    // physics: thread -> sample pm, 16 buses
    const int pm = tid >> 1;
    const int pb = (tid & 1) * 16;
    #pragma unroll
    for (int g4 = 0; g4 < 4; g4++) {
        float4 vo, vt, vp4;
        float* po = &vo.x; float* pt = &vt.x; float* pp = &vp4.x;
        const float4 pw = __ldg((const float4*)(power + (size_t)(base + pm) * NBUS + pb + g4 * 4));
        const float* ppw = &pw.x;
        #pragma unroll
        for (int e = 0; e < 4; e++) {
            const int bus = pb + g4 * 4 + e;
            const float o   = f_o  [pm * NBUS + bus];
            const float ot  = f_ot [pm * NBUS + bus];
            const float ott = f_ott[pm * NBUS + bus];
            float accC = 0.0f, accS = 0.0f;
            #pragma unroll
            for (int j = 0; j < NBUS; j++) {
                const float bl2 = __ldg(&lam_b[bus * NBUS + j]);
                accC = fmaf(bl2, scc[pm * 33 + j], accC);
                accS = fmaf(bl2, scs[pm * 33 + j], accS);
            }
            const float conn = scs[pm * 33 + bus] * accC - scc[pm * 33 + bus] * accS;
            const float lm = __ldg(&lam_m[bus]) * __ldg(&bwi[bus]);
            const float ld = __ldg(&lam_d[bus]);
            po[e] = o;
            pt[e] = ot;
            pp[e] = fmaf(lm, ott, fmaf(ld, ot, conn - ppw[e]));
        }
        const size_t gi = (size_t)(base + pm) * NBUS + pb + g4 * 4;
        *(float4*)(out_d  + gi) = vo;
        *(float4*)(out_dt + gi) = vt;
        *(float4*)(out_ph + gi) = vp4;
    }
}

extern "C" void kernel_launch(void* const* d_in, const int* in_sizes, int n_in,
                              void* d_out, int out_size) {
    const float* t_in  = (const float*)d_in[0];
    const float* power = (const float*)d_in[1];
    const float* W0    = (const float*)d_in[2];
    const float* b0    = (const float*)d_in[3];
    const float* W1    = (const float*)d_in[4];
    const float* b1    = (const float*)d_in[5];
    const float* W2    = (const float*)d_in[6];
    const float* b2    = (const float*)d_in[7];
    const float* lam_m = (const float*)d_in[8];
    const float* lam_d = (const float*)d_in[9];
    const float* lam_b = (const float*)d_in[10];
    const float* bwi   = (const float*)d_in[11];

    float* out  = (float*)d_out;
    float* outt = out  + (size_t)NS * NBUS;
    float* outp = outt + (size_t)NS * NBUS;

    prep_kernel<<<32, 256>>>(W1, W2);

    cudaFuncSetAttribute(pinn_l1_kernel, cudaFuncAttributeMaxDynamicSharedMemorySize, SMEM_TOTAL);
    pinn_l1_kernel<<<NCTA, THREADS, SMEM_TOTAL>>>(t_in, W0, b0, b1);

    cudaFuncSetAttribute(pinn_l2_kernel, cudaFuncAttributeMaxDynamicSharedMemorySize, K2_SMEM);
    pinn_l2_kernel<<<NCTA2, THREADS, K2_SMEM>>>(power, b2, lam_m, lam_d, lam_b, bwi,
                                                out, outt, outp);
}